// round 14
// baseline (speedup 1.0000x reference)
#include <cuda_runtime.h>
#include <cstdint>
#include <math.h>

#define N_NODES 50000
#define N_EDGES 800000
#define ESC 50
#define SQRT3F 1.7320508075688772f
#define TP_NORM 0.125f
#define INV_SQRT32 0.17677669529663687f
#define INV_SQRT119 0.09166984970282113f
#define NT 6250

// smem offsets (floats)
#define O_SB0 0
#define O_SB1 16384
#define O_EL  32768
#define O_BC  40448
#define O_VS  42752
#define O_VV  44032
#define O_RW  45312
#define O_SR  52928
#define O_EV  53440
#define SMEM_FLOATS 53952
#define SMEM_BYTES (SMEM_FLOATS * 4)

__device__ float4 g_state[N_NODES * 32];  // {s, vx, vy, vz} per (node, channel)
__device__ float4 g_agg[N_NODES * 32];    // {s, vx, vy, vz}

__device__ __forceinline__ float sigmoidf_(float x) { return 1.0f / (1.0f + __expf(-x)); }
__device__ __forceinline__ float warp_sum(float v) {
    #pragma unroll
    for (int o = 16; o > 0; o >>= 1) v += __shfl_xor_sync(0xFFFFFFFFu, v, o);
    return v;
}
__device__ __forceinline__ float tf32f(float f) {
    uint32_t r; asm("cvt.rna.tf32.f32 %0, %1;" : "=r"(r) : "f"(f));
    return __uint_as_float(r);
}
__device__ __forceinline__ void cpa4(float* smem_dst, const float* gsrc) {
    uint32_t a = (uint32_t)__cvta_generic_to_shared(smem_dst);
    asm volatile("cp.async.ca.shared.global [%0], [%1], 4;" :: "r"(a), "l"(gsrc));
}
__device__ __forceinline__ void cpa16(float* smem_dst, const float4* gsrc) {
    uint32_t a = (uint32_t)__cvta_generic_to_shared(smem_dst);
    asm volatile("cp.async.cg.shared.global [%0], [%1], 16;" :: "r"(a), "l"(gsrc));
}
#define CP_COMMIT() asm volatile("cp.async.commit_group;" ::: "memory")
#define CP_WAIT0()  asm volatile("cp.async.wait_group 0;" ::: "memory")

#define MMA8(D, a0, a1, a2, a3, b0, b1) \
    asm volatile("mma.sync.aligned.m16n8k8.row.col.f32.tf32.tf32.f32 " \
        "{%0,%1,%2,%3}, {%4,%5,%6,%7}, {%8,%9}, {%0,%1,%2,%3};" \
        : "+f"((D)[0]), "+f"((D)[1]), "+f"((D)[2]), "+f"((D)[3]) \
        : "r"(a0), "r"(a1), "r"(a2), "r"(a3), "r"(b0), "r"(b1))

#define BARP(id) asm volatile("bar.sync %0, %1;" :: "r"(id), "r"(64) : "memory")

__device__ __forceinline__ void warp_process(
    float& s, float& vx, float& vy, float& vz, int lane, float* stage32, int st,
    const float* __restrict__ lng, const float* __restrict__ lnb,
    const float* __restrict__ Gw, const float* __restrict__ Gb)
{
    float m = warp_sum(s) * (1.0f / 32.0f);
    float d = s - m;
    float var = warp_sum(d * d) * (1.0f / 32.0f);
    float sn = d * rsqrtf(var + 1e-5f) * __ldg(lng + st * 32 + lane) + __ldg(lnb + st * 32 + lane);
    float a = sn * sigmoidf_(sn);
    __syncwarp();
    stage32[lane] = a;
    __syncwarp();
    float g = __ldg(Gb + st * 32 + lane);
    const float* gw = Gw + st * 1024;
    #pragma unroll 8
    for (int i = 0; i < 32; i++) g += stage32[i] * __ldg(gw + i * 32 + lane);
    g = sigmoidf_(g);
    s = a; vx *= g; vy *= g; vz *= g;
}

__global__ void k_embed(const float* __restrict__ x, const float* __restrict__ deg,
                        const float* __restrict__ pos,
                        const float* __restrict__ Wes, const float* __restrict__ Wev,
                        const float* __restrict__ lng, const float* __restrict__ lnb,
                        const float* __restrict__ Gw, const float* __restrict__ Gb)
{
    __shared__ float sStage[4][32];
    int w = threadIdx.x >> 5, lane = threadIdx.x & 31;
    int n = blockIdx.x * 4 + w;
    if (n >= N_NODES) return;
    const float2* xr2 = (const float2*)(x + (size_t)n * 118);
    float acc = 0.0f;
    #pragma unroll 4
    for (int i = 0; i < 59; i++) {
        float2 v = __ldg(xr2 + i);
        acc += v.x * __ldg(Wes + (2 * i) * 32 + lane);
        acc += v.y * __ldg(Wes + (2 * i + 1) * 32 + lane);
    }
    acc += __ldg(deg + n) * __ldg(Wes + 118 * 32 + lane);
    float s = acc * INV_SQRT119;
    float wv = __ldg(Wev + lane);
    float vx = __ldg(pos + n * 3 + 0) * wv;
    float vy = __ldg(pos + n * 3 + 1) * wv;
    float vz = __ldg(pos + n * 3 + 2) * wv;
    warp_process(s, vx, vy, vz, lane, sStage[w], 0, lng, lnb, Gw, Gb);
    g_state[n * 32 + lane] = make_float4(s, vx, vy, vz);
    g_agg[n * 32 + lane] = make_float4(0.f, 0.f, 0.f, 0.f);
}

// ---------------- fused edge kernel: SB double-buffer feeds MMA A directly ----------------
__global__ void __launch_bounds__(512, 1) k_edge(
    const int* __restrict__ eidx, const float* __restrict__ evec,
    const float* __restrict__ elen,
    const float* __restrict__ Wss, const float* __restrict__ Wvs,
    const float* __restrict__ Wsv, const float* __restrict__ Wvv,
    const float* __restrict__ Rw, const float* __restrict__ Rb)
{
    extern __shared__ float sm[];
    float* SB0 = sm + O_SB0;  // [128 rows][32 ch x float4], chunk XOR-swizzled
    float* SB1 = sm + O_SB1;
    float* EL = sm + O_EL;    // [128][60] raw f32 (cols 50..59 zero)
    float* BC = sm + O_BC;    // [32][72]
    float* VS = sm + O_VS;    // [32][40]
    float* VV = sm + O_VV;    // [32][40]
    float* RW = sm + O_RW;    // [56][136] permuted
    float4* SR4 = (float4*)(sm + O_SR);  // [128] {rx,ry,rz,dst}
    float* EV = sm + O_EV;    // [128][4]

    int tid = threadIdx.x, w = tid >> 5, lane = tid & 31;
    int pair = w >> 1, p = w & 1;
    int g = lane >> 2, c = lane & 3;
    int r0 = pair << 4;
    int rb8 = r0 + (p << 3);
    int barid = 8 + pair;

    // ---- one-time B-tile init ----
    for (int i = tid; i < 56 * 136; i += 512) {
        int k = i / 136, n = i % 136;
        float v = 0.f;
        if (k < ESC && n < 128) {
            int ch = n & 31, m = n >> 5;
            int col = (m == 0) ? ch : 32 + 3 * ch + (m - 1);
            v = __ldg(Rw + k * 128 + col);
        }
        RW[i] = tf32f(v);
    }
    for (int i = tid; i < 32 * 72; i += 512) {
        int k = i / 72, n = i % 72;
        float v = (n < 32) ? __ldg(Wss + k * 32 + n) : ((n < 64) ? __ldg(Wsv + k * 32 + n - 32) : 0.f);
        BC[i] = tf32f(v);
    }
    for (int i = tid; i < 32 * 40; i += 512) {
        int k = i / 40, n = i % 40;
        VS[i] = (n < 32) ? tf32f(__ldg(Wvs + k * 32 + n)) : 0.f;
        VV[i] = (n < 32) ? tf32f(__ldg(Wvv + k * 32 + n)) : 0.f;
    }
    for (int i = tid; i < 128 * 10; i += 512)
        EL[(i / 10) * 60 + 50 + (i % 10)] = 0.f;
    __syncthreads();

    // per-lane radial biases: rbv[comp][qq][u]
    float rbv[4][2][2];
    #pragma unroll
    for (int m = 0; m < 4; m++)
        #pragma unroll
        for (int qq = 0; qq < 2; qq++)
            #pragma unroll
            for (int u = 0; u < 2; u++) {
                int ch = 16 * p + 8 * qq + 2 * c + u;
                int col = (m == 0) ? ch : 32 + 3 * ch + (m - 1);
                rbv[m][qq][u] = __ldg(Rb + col);
            }

    int dV = 0, sVn = 0, dVn = 0;
    // SB write chunk for this lane, by row parity (rb8+j: parity = j&1)
    int cpEven = lane;          // row even
    int cpOdd  = lane ^ 4;      // row odd

    // ---- prologue: gather tile t0 into SB0; preload indices for t0, t1 ----
    int t0 = blockIdx.x;
    {
        int sV0 = 0;
        if (lane < 8 && t0 < NT) {
            sV0 = __ldg(eidx + t0 * 128 + rb8 + lane);
            dV  = __ldg(eidx + N_EDGES + t0 * 128 + rb8 + lane);
        }
        if (t0 < NT) {
            int e0n = t0 * 128;
            #pragma unroll
            for (int j = 0; j < 8; j++) {
                int src = __shfl_sync(0xFFFFFFFFu, sV0, j);
                int row = rb8 + j;
                int cp = (j & 1) ? cpOdd : cpEven;
                cpa16(SB0 + row * 128 + cp * 4, &g_state[src * 32 + lane]);
                size_t e = (size_t)(e0n + row);
                cpa4(EL + row * 60 + lane, elen + e * ESC + lane);
                if (lane < ESC - 32)
                    cpa4(EL + row * 60 + 32 + lane, elen + e * ESC + 32 + lane);
            }
            if (lane < 24)   // 8 rows x 3 comps; contiguous in evec
                cpa4(EV + (rb8 + lane / 3) * 4 + (lane % 3),
                     evec + (size_t)(e0n + rb8) * 3 + lane);
            CP_COMMIT();
        }
        if (lane < 8 && t0 + (int)gridDim.x < NT) {
            sVn = __ldg(eidx + (t0 + gridDim.x) * 128 + rb8 + lane);
            dVn = __ldg(eidx + N_EDGES + (t0 + gridDim.x) * 128 + rb8 + lane);
        }
    }

    int it = 0;
    for (int t = t0; t < NT; t += gridDim.x, it++) {
        float* SBc = (it & 1) ? SB1 : SB0;   // current tile's gather
        float* SBn = (it & 1) ? SB0 : SB1;   // next tile's target
        CP_WAIT0();            // SB/EV/EL for tile t complete
        BARP(barid);           // partner done with previous SR/SB reads; its cp.asyncs drained

        // ---- SR: lane j<8 owns row rb8+j (has its own dst in dV) ----
        if (lane < 8) {
            int row = rb8 + lane;
            float vx = EV[row * 4], vy = EV[row * 4 + 1], vz = EV[row * 4 + 2];
            float inv = rsqrtf(vx * vx + vy * vy + vz * vz);
            SR4[row] = make_float4(vx * inv, vy * inv, vz * inv, __int_as_float(dV));
        }
        // ---- SB/EV prefetch for t+1 into SBn ----
        if (t + (int)gridDim.x < NT) {
            int e0n = (t + gridDim.x) * 128;
            #pragma unroll
            for (int j = 0; j < 8; j++) {
                int src = __shfl_sync(0xFFFFFFFFu, sVn, j);
                int row = rb8 + j;
                int cp = (j & 1) ? cpOdd : cpEven;
                cpa16(SBn + row * 128 + cp * 4, &g_state[src * 32 + lane]);
            }
            if (lane < 24)
                cpa4(EV + (rb8 + lane / 3) * 4 + (lane % 3),
                     evec + (size_t)(e0n + rb8) * 3 + lane);
            CP_COMMIT();
        }
        BARP(barid);           // SR visible to pair

        // ---- phase 1: radial GEMM (EL raw f32 A, RW B) ----
        float Cr[8][4];
        #pragma unroll
        for (int i = 0; i < 8; i++) { Cr[i][0] = Cr[i][1] = Cr[i][2] = Cr[i][3] = 0.f; }
        #pragma unroll
        for (int k = 0; k < 7; k++) {
            int k0 = k << 3;
            const float* ab = EL + (r0 + g) * 60 + k0 + c;
            uint32_t a0 = __float_as_uint(ab[0]);
            uint32_t a1 = __float_as_uint(ab[8 * 60]);
            uint32_t a2 = __float_as_uint(ab[4]);
            uint32_t a3 = __float_as_uint(ab[8 * 60 + 4]);
            #pragma unroll
            for (int q = 0; q < 8; q++) {
                int ntg = ((q >> 1) << 2) + (p << 1) + (q & 1);
                const float* bb = RW + (k0 + c) * 136 + (ntg << 3) + g;
                uint32_t b0 = __float_as_uint(bb[0]);
                uint32_t b1 = __float_as_uint(bb[4 * 136]);
                MMA8(Cr[q], a0, a1, a2, a3, b0, b1);
            }
        }
        BARP(barid);           // pair done reading EL -> safe to refill

        // ---- EL prefetch for t+1 ----
        if (t + (int)gridDim.x < NT) {
            int e0n = (t + gridDim.x) * 128;
            #pragma unroll
            for (int j = 0; j < 8; j++) {
                int row = rb8 + j;
                size_t e = (size_t)(e0n + row);
                cpa4(EL + row * 60 + lane, elen + e * ESC + lane);
                if (lane < ESC - 32)
                    cpa4(EL + row * 60 + 32 + lane, elen + e * ESC + 32 + lane);
            }
            CP_COMMIT();
        }
        dV = dVn;
        sVn = 0; dVn = 0;
        if (lane < 8 && t + 2 * (int)gridDim.x < NT) {
            sVn = __ldg(eidx + (t + 2 * gridDim.x) * 128 + rb8 + lane);
            dVn = __ldg(eidx + N_EDGES + (t + 2 * gridDim.x) * 128 + rb8 + lane);
        }

        // ---- phase 2: TP GEMMs, A direct from SBc via LDS.128 (raw f32 -> tf32 trunc) ----
        float4 rrl = SR4[r0 + g];
        float4 rrh = SR4[r0 + g + 8];
        int swz = (g & 1) << 2;
        #pragma unroll
        for (int q = 0; q < 2; q++) {
            int nt = (p << 1) + q;
            float cs1[4] = {0,0,0,0}, cs2[4] = {0,0,0,0};
            float cpx[4] = {0,0,0,0}, cpy[4] = {0,0,0,0}, cpz[4] = {0,0,0,0};
            float cax[4] = {0,0,0,0}, cay[4] = {0,0,0,0}, caz[4] = {0,0,0,0};
            #pragma unroll
            for (int k = 0; k < 4; k++) {
                int k0 = k << 3;
                int chA = (k0 + c) ^ swz;
                int chB = chA ^ 4;
                float4 Ala = *(const float4*)(SBc + (r0 + g) * 128 + chA * 4);
                float4 Aha = *(const float4*)(SBc + (r0 + g + 8) * 128 + chA * 4);
                float4 Alb = *(const float4*)(SBc + (r0 + g) * 128 + chB * 4);
                float4 Ahb = *(const float4*)(SBc + (r0 + g + 8) * 128 + chB * 4);
                uint32_t s0 = __float_as_uint(Ala.x), s1 = __float_as_uint(Aha.x);
                uint32_t s2 = __float_as_uint(Alb.x), s3 = __float_as_uint(Ahb.x);
                uint32_t x0 = __float_as_uint(Ala.y), x1 = __float_as_uint(Aha.y);
                uint32_t x2 = __float_as_uint(Alb.y), x3 = __float_as_uint(Ahb.y);
                uint32_t y0 = __float_as_uint(Ala.z), y1 = __float_as_uint(Aha.z);
                uint32_t y2 = __float_as_uint(Alb.z), y3 = __float_as_uint(Ahb.z);
                uint32_t z0 = __float_as_uint(Ala.w), z1 = __float_as_uint(Aha.w);
                uint32_t z2 = __float_as_uint(Alb.w), z3 = __float_as_uint(Ahb.w);

                const float* bb = BC + (k0 + c) * 72 + (nt << 3) + g;
                uint32_t bc10 = __float_as_uint(bb[0]), bc11 = __float_as_uint(bb[4 * 72]);
                uint32_t bc20 = __float_as_uint(bb[32]), bc21 = __float_as_uint(bb[4 * 72 + 32]);
                bb = VS + (k0 + c) * 40 + (nt << 3) + g;
                uint32_t vs0 = __float_as_uint(bb[0]), vs1 = __float_as_uint(bb[4 * 40]);
                bb = VV + (k0 + c) * 40 + (nt << 3) + g;
                uint32_t vv0 = __float_as_uint(bb[0]), vv1 = __float_as_uint(bb[4 * 40]);

                MMA8(cs1, s0, s1, s2, s3, bc10, bc11);
                MMA8(cs2, s0, s1, s2, s3, bc20, bc21);
                MMA8(cpx, x0, x1, x2, x3, vs0, vs1);
                MMA8(cpy, y0, y1, y2, y3, vs0, vs1);
                MMA8(cpz, z0, z1, z2, z3, vs0, vs1);
                MMA8(cax, x0, x1, x2, x3, vv0, vv1);
                MMA8(cay, y0, y1, y2, y3, vv0, vv1);
                MMA8(caz, z0, z1, z2, z3, vv0, vv1);
            }
            #pragma unroll
            for (int h = 0; h < 2; h++) {
                float4 rr = h ? rrh : rrl;
                int dst = __float_as_int(rr.w);
                float Yx = SQRT3F * rr.x, Yy = SQRT3F * rr.y, Yz = SQRT3F * rr.z;
                #pragma unroll
                for (int u = 0; u < 2; u++) {
                    int idx = (h << 1) + u;
                    int ch = (nt << 3) + 2 * c + u;
                    float gs = sigmoidf_(Cr[q][idx]     + rbv[0][q][u]);
                    float gx = sigmoidf_(Cr[2 + q][idx] + rbv[1][q][u]);
                    float gy = sigmoidf_(Cr[4 + q][idx] + rbv[2][q][u]);
                    float gz = sigmoidf_(Cr[6 + q][idx] + rbv[3][q][u]);
                    float sOut = (cs1[idx] + rr.x * cpx[idx] + rr.y * cpy[idx]
                                + rr.z * cpz[idx]) * TP_NORM * gs;
                    float sv = cs2[idx];
                    float ovx = (sv * Yx + cax[idx]) * TP_NORM * gx;
                    float ovy = (sv * Yy + cay[idx]) * TP_NORM * gy;
                    float ovz = (sv * Yz + caz[idx]) * TP_NORM * gz;
                    float4* ap = &g_agg[dst * 32 + ch];
                    asm volatile("red.global.add.v4.f32 [%0], {%1,%2,%3,%4};"
                        :: "l"(ap), "f"(sOut), "f"(ovx), "f"(ovy), "f"(ovz) : "memory");
                }
            }
        }
    }
}

__global__ void k_node(const float* __restrict__ Ls, const float* __restrict__ Lv,
                       int stage,
                       const float* __restrict__ lng, const float* __restrict__ lnb,
                       const float* __restrict__ Gw, const float* __restrict__ Gb)
{
    __shared__ float sS[4][32];
    __shared__ float sV[4][3][32];
    int w = threadIdx.x >> 5, lane = threadIdx.x & 31;
    int n = blockIdx.x * 4 + w;
    if (n >= N_NODES) return;

    float4 ag = g_agg[n * 32 + lane];
    g_agg[n * 32 + lane] = make_float4(0.f, 0.f, 0.f, 0.f);
    float4 st = g_state[n * 32 + lane];
    sS[w][lane] = st.x + ag.x;
    sV[w][0][lane] = st.y + ag.y;
    sV[w][1][lane] = st.z + ag.z;
    sV[w][2][lane] = st.w + ag.w;
    __syncwarp();

    float ns = 0.0f, nvx = 0.0f, nvy = 0.0f, nvz = 0.0f;
    #pragma unroll 8
    for (int i = 0; i < 32; i++) {
        int o = i * 32 + lane;
        ns += sS[w][i] * __ldg(Ls + o);
        float lw = __ldg(Lv + o);
        nvx += sV[w][0][i] * lw; nvy += sV[w][1][i] * lw; nvz += sV[w][2][i] * lw;
    }
    ns *= INV_SQRT32; nvx *= INV_SQRT32; nvy *= INV_SQRT32; nvz *= INV_SQRT32;
    __syncwarp();
    warp_process(ns, nvx, nvy, nvz, lane, sS[w], stage, lng, lnb, Gw, Gb);
    g_state[n * 32 + lane] = make_float4(ns, nvx, nvy, nvz);
}

__global__ void k_out(const float* __restrict__ Os, const float* __restrict__ Ov,
                      const float* __restrict__ lng, const float* __restrict__ lnb,
                      const float* __restrict__ Gw, const float* __restrict__ Gb,
                      const float* __restrict__ Psw, const float* __restrict__ Psb,
                      const float* __restrict__ Pvw, const float* __restrict__ Pvb,
                      float* __restrict__ out)
{
    __shared__ float sS[4][32];
    __shared__ float sV[4][3][32];
    int w = threadIdx.x >> 5, lane = threadIdx.x & 31;
    int n = blockIdx.x * 4 + w;
    if (n >= N_NODES) return;

    float4 st = g_state[n * 32 + lane];
    sS[w][lane] = st.x;
    sV[w][0][lane] = st.y;
    sV[w][1][lane] = st.z;
    sV[w][2][lane] = st.w;
    __syncwarp();

    float ns = 0.0f, nvx = 0.0f, nvy = 0.0f, nvz = 0.0f;
    #pragma unroll 8
    for (int i = 0; i < 32; i++) {
        int o = i * 32 + lane;
        ns += sS[w][i] * __ldg(Os + o);
        float lw = __ldg(Ov + o);
        nvx += sV[w][0][i] * lw; nvy += sV[w][1][i] * lw; nvz += sV[w][2][i] * lw;
    }
    ns *= INV_SQRT32; nvx *= INV_SQRT32; nvy *= INV_SQRT32; nvz *= INV_SQRT32;
    __syncwarp();
    warp_process(ns, nvx, nvy, nvz, lane, sS[w], 3, lng, lnb, Gw, Gb);
    __syncwarp();
    sV[w][0][lane] = nvx; sV[w][1][lane] = nvy; sV[w][2][lane] = nvz;
    __syncwarp();

    float sc0 = 0.f, sc1 = 0.f, t00 = 0.f, t01 = 0.f, t10 = 0.f, t11 = 0.f, t20 = 0.f, t21 = 0.f;
    #pragma unroll 8
    for (int i = 0; i < 32; i++) {
        float si = sS[w][i];
        float vx = sV[w][0][i], vy = sV[w][1][i], vz = sV[w][2][i];
        float pw0 = __ldg(Psw + i * 64 + lane), pw1 = __ldg(Psw + i * 64 + 32 + lane);
        float qw0 = __ldg(Pvw + i * 64 + lane), qw1 = __ldg(Pvw + i * 64 + 32 + lane);
        sc0 += si * pw0; sc1 += si * pw1;
        t00 += vx * qw0; t01 += vx * qw1;
        t10 += vy * qw0; t11 += vy * qw1;
        t20 += vz * qw0; t21 += vz * qw1;
    }
    float base0 = sc0 + __ldg(Psb + lane) + __ldg(Pvb + lane);
    float base1 = sc1 + __ldg(Psb + 32 + lane) + __ldg(Pvb + 32 + lane);
    size_t ob = (size_t)n * 192;
    out[ob + lane]       = t00 + base0;
    out[ob + 32 + lane]  = t01 + base1;
    out[ob + 64 + lane]  = t10 + base0;
    out[ob + 96 + lane]  = t11 + base1;
    out[ob + 128 + lane] = t20 + base0;
    out[ob + 160 + lane] = t21 + base1;
}

extern "C" void kernel_launch(void* const* d_in, const int* in_sizes, int n_in,
                              void* d_out, int out_size)
{
    const float* x    = (const float*)d_in[0];
    const float* deg  = (const float*)d_in[1];
    const float* pos  = (const float*)d_in[2];
    const float* evec = (const float*)d_in[3];
    const float* elen = (const float*)d_in[4];
    const int*   eidx = (const int*)d_in[5];
    const float* Wes  = (const float*)d_in[6];
    const float* Wev  = (const float*)d_in[7];
    const float* Wss  = (const float*)d_in[8];
    const float* Wvs  = (const float*)d_in[9];
    const float* Wsv  = (const float*)d_in[10];
    const float* Wvv  = (const float*)d_in[11];
    const float* Ls   = (const float*)d_in[12];
    const float* Lv   = (const float*)d_in[13];
    const float* Rw   = (const float*)d_in[14];
    const float* Rb   = (const float*)d_in[15];
    const float* lng  = (const float*)d_in[16];
    const float* lnb  = (const float*)d_in[17];
    const float* Gw   = (const float*)d_in[18];
    const float* Gb   = (const float*)d_in[19];
    const float* Os   = (const float*)d_in[20];
    const float* Ov   = (const float*)d_in[21];
    const float* Psw  = (const float*)d_in[22];
    const float* Psb  = (const float*)d_in[23];
    const float* Pvw  = (const float*)d_in[24];
    const float* Pvb  = (const float*)d_in[25];
    float* out = (float*)d_out;

    static int smem_set = 0;
    if (!smem_set) {
        cudaFuncSetAttribute(k_edge, cudaFuncAttributeMaxDynamicSharedMemorySize, SMEM_BYTES);
        smem_set = 1;
    }

    int node_blocks = (N_NODES + 3) / 4;
    k_embed<<<node_blocks, 128>>>(x, deg, pos, Wes, Wev, lng, lnb, Gw, Gb);
    for (int l = 0; l < 2; l++) {
        k_edge<<<148, 512, SMEM_BYTES>>>(eidx, evec, elen,
                                         Wss + l * 1024, Wvs + l * 1024,
                                         Wsv + l * 1024, Wvv + l * 1024,
                                         Rw + l * ESC * 128, Rb + l * 128);
        k_node<<<node_blocks, 128>>>(Ls + l * 1024, Lv + l * 1024, l + 1, lng, lnb, Gw, Gb);
    }
    k_out<<<node_blocks, 128>>>(Os, Ov, lng, lnb, Gw, Gb, Psw, Psb, Pvw, Pvb, out);
}

// round 15
// speedup vs baseline: 1.3978x; 1.3978x over previous
#include <cuda_runtime.h>
#include <cstdint>
#include <math.h>

#define N_NODES 50000
#define N_EDGES 800000
#define ESC 50
#define SQRT3F 1.7320508075688772f
#define TP_NORM 0.125f
#define INV_SQRT32 0.17677669529663687f
#define INV_SQRT119 0.09166984970282113f
#define NT 6250

// smem offsets (floats)
#define O_MS 0
#define O_MX 4608
#define O_MY 9216
#define O_MZ 13824
#define O_EL 18432
#define O_BC 26112
#define O_VS 28416
#define O_VV 29696
#define O_RW 30976
#define O_SR 38592
#define O_SB 39104
#define O_EV 55488
#define SMEM_FLOATS 56000
#define SMEM_BYTES (SMEM_FLOATS * 4)

__device__ float4 g_state[N_NODES * 32];  // {s, vx, vy, vz} per (node, channel)
__device__ float4 g_agg[N_NODES * 32];    // {s, vx, vy, vz}

__device__ __forceinline__ float sigmoidf_(float x) { return 1.0f / (1.0f + __expf(-x)); }
__device__ __forceinline__ float warp_sum(float v) {
    #pragma unroll
    for (int o = 16; o > 0; o >>= 1) v += __shfl_xor_sync(0xFFFFFFFFu, v, o);
    return v;
}
__device__ __forceinline__ float tf32f(float f) {
    uint32_t r; asm("cvt.rna.tf32.f32 %0, %1;" : "=r"(r) : "f"(f));
    return __uint_as_float(r);
}
__device__ __forceinline__ void cpa4(float* smem_dst, const float* gsrc) {
    uint32_t a = (uint32_t)__cvta_generic_to_shared(smem_dst);
    asm volatile("cp.async.ca.shared.global [%0], [%1], 4;" :: "r"(a), "l"(gsrc));
}
__device__ __forceinline__ void cpa16(float* smem_dst, const float4* gsrc) {
    uint32_t a = (uint32_t)__cvta_generic_to_shared(smem_dst);
    asm volatile("cp.async.cg.shared.global [%0], [%1], 16;" :: "r"(a), "l"(gsrc));
}
#define CP_COMMIT() asm volatile("cp.async.commit_group;" ::: "memory")
#define CP_WAIT0()  asm volatile("cp.async.wait_group 0;" ::: "memory")

#define MMA8(D, a0, a1, a2, a3, b0, b1) \
    asm volatile("mma.sync.aligned.m16n8k8.row.col.f32.tf32.tf32.f32 " \
        "{%0,%1,%2,%3}, {%4,%5,%6,%7}, {%8,%9}, {%0,%1,%2,%3};" \
        : "+f"((D)[0]), "+f"((D)[1]), "+f"((D)[2]), "+f"((D)[3]) \
        : "r"(a0), "r"(a1), "r"(a2), "r"(a3), "r"(b0), "r"(b1))

#define BARP(id) asm volatile("bar.sync %0, %1;" :: "r"(id), "r"(64) : "memory")

__device__ __forceinline__ void warp_process(
    float& s, float& vx, float& vy, float& vz, int lane, float* stage32, int st,
    const float* __restrict__ lng, const float* __restrict__ lnb,
    const float* __restrict__ Gw, const float* __restrict__ Gb)
{
    float m = warp_sum(s) * (1.0f / 32.0f);
    float d = s - m;
    float var = warp_sum(d * d) * (1.0f / 32.0f);
    float sn = d * rsqrtf(var + 1e-5f) * __ldg(lng + st * 32 + lane) + __ldg(lnb + st * 32 + lane);
    float a = sn * sigmoidf_(sn);
    __syncwarp();
    stage32[lane] = a;
    __syncwarp();
    float g = __ldg(Gb + st * 32 + lane);
    const float* gw = Gw + st * 1024;
    #pragma unroll 8
    for (int i = 0; i < 32; i++) g += stage32[i] * __ldg(gw + i * 32 + lane);
    g = sigmoidf_(g);
    s = a; vx *= g; vy *= g; vz *= g;
}

__global__ void k_embed(const float* __restrict__ x, const float* __restrict__ deg,
                        const float* __restrict__ pos,
                        const float* __restrict__ Wes, const float* __restrict__ Wev,
                        const float* __restrict__ lng, const float* __restrict__ lnb,
                        const float* __restrict__ Gw, const float* __restrict__ Gb)
{
    __shared__ float sStage[4][32];
    int w = threadIdx.x >> 5, lane = threadIdx.x & 31;
    int n = blockIdx.x * 4 + w;
    if (n >= N_NODES) return;
    const float2* xr2 = (const float2*)(x + (size_t)n * 118);
    float acc = 0.0f;
    #pragma unroll 4
    for (int i = 0; i < 59; i++) {
        float2 v = __ldg(xr2 + i);
        acc += v.x * __ldg(Wes + (2 * i) * 32 + lane);
        acc += v.y * __ldg(Wes + (2 * i + 1) * 32 + lane);
    }
    acc += __ldg(deg + n) * __ldg(Wes + 118 * 32 + lane);
    float s = acc * INV_SQRT119;
    float wv = __ldg(Wev + lane);
    float vx = __ldg(pos + n * 3 + 0) * wv;
    float vy = __ldg(pos + n * 3 + 1) * wv;
    float vz = __ldg(pos + n * 3 + 2) * wv;
    warp_process(s, vx, vy, vz, lane, sStage[w], 0, lng, lnb, Gw, Gb);
    g_state[n * 32 + lane] = make_float4(s, vx, vy, vz);
    g_agg[n * 32 + lane] = make_float4(0.f, 0.f, 0.f, 0.f);
}

// ---------------- fused edge kernel (R13 structure + staging cleanups) ----------------
__global__ void __launch_bounds__(512, 1) k_edge(
    const int* __restrict__ eidx, const float* __restrict__ evec,
    const float* __restrict__ elen,
    const float* __restrict__ Wss, const float* __restrict__ Wvs,
    const float* __restrict__ Wsv, const float* __restrict__ Wvv,
    const float* __restrict__ Rw, const float* __restrict__ Rb)
{
    extern __shared__ float sm[];
    float* MS = sm + O_MS;   // [128][36] tf32
    float* MX = sm + O_MX;
    float* MY = sm + O_MY;
    float* MZ = sm + O_MZ;
    float* EL = sm + O_EL;   // [128][60] raw f32 (cols 50..59 zero)
    float* BC = sm + O_BC;   // [32][72]
    float* VS = sm + O_VS;   // [32][40]
    float* VV = sm + O_VV;   // [32][40]
    float* RW = sm + O_RW;   // [56][136] permuted
    float4* SR4 = (float4*)(sm + O_SR);  // [128] {rx,ry,rz,dst}
    float* SB = sm + O_SB;   // [128][32] float4 raw state, warp-private rows
    float* EV = sm + O_EV;   // [128][4]  evec

    int tid = threadIdx.x, w = tid >> 5, lane = tid & 31;
    int pair = w >> 1, p = w & 1;
    int g = lane >> 2, c = lane & 3;
    int r0 = pair << 4;
    int rb8 = r0 + (p << 3);
    int barid = 8 + pair;

    // ---- one-time B-tile init ----
    for (int i = tid; i < 56 * 136; i += 512) {
        int k = i / 136, n = i % 136;
        float v = 0.f;
        if (k < ESC && n < 128) {
            int ch = n & 31, m = n >> 5;
            int col = (m == 0) ? ch : 32 + 3 * ch + (m - 1);
            v = __ldg(Rw + k * 128 + col);
        }
        RW[i] = tf32f(v);
    }
    for (int i = tid; i < 32 * 72; i += 512) {
        int k = i / 72, n = i % 72;
        float v = (n < 32) ? __ldg(Wss + k * 32 + n) : ((n < 64) ? __ldg(Wsv + k * 32 + n - 32) : 0.f);
        BC[i] = tf32f(v);
    }
    for (int i = tid; i < 32 * 40; i += 512) {
        int k = i / 40, n = i % 40;
        VS[i] = (n < 32) ? tf32f(__ldg(Wvs + k * 32 + n)) : 0.f;
        VV[i] = (n < 32) ? tf32f(__ldg(Wvv + k * 32 + n)) : 0.f;
    }
    for (int i = tid; i < 128 * 10; i += 512)
        EL[(i / 10) * 60 + 50 + (i % 10)] = 0.f;
    __syncthreads();

    // per-lane radial biases: rbv[comp][qq][u]
    float rbv[4][2][2];
    #pragma unroll
    for (int m = 0; m < 4; m++)
        #pragma unroll
        for (int qq = 0; qq < 2; qq++)
            #pragma unroll
            for (int u = 0; u < 2; u++) {
                int ch = 16 * p + 8 * qq + 2 * c + u;
                int col = (m == 0) ? ch : 32 + 3 * ch + (m - 1);
                rbv[m][qq][u] = __ldg(Rb + col);
            }

    int dV = 0, sVn = 0, dVn = 0;

    // ---- prologue: gather tile t0 via cp.async; preload indices for t0 and t1 ----
    int t0 = blockIdx.x;
    {
        int sV0 = 0;
        if (lane < 8 && t0 < NT) {
            sV0 = __ldg(eidx + t0 * 128 + rb8 + lane);
            dV  = __ldg(eidx + N_EDGES + t0 * 128 + rb8 + lane);
        }
        if (t0 < NT) {
            int e0n = t0 * 128;
            #pragma unroll
            for (int j = 0; j < 8; j++) {
                int src = __shfl_sync(0xFFFFFFFFu, sV0, j);
                int row = rb8 + j;
                size_t e = (size_t)(e0n + row);
                cpa16(SB + (row * 32 + lane) * 4, &g_state[src * 32 + lane]);
                cpa4(EL + row * 60 + lane, elen + e * ESC + lane);
                if (lane < ESC - 32)
                    cpa4(EL + row * 60 + 32 + lane, elen + e * ESC + 32 + lane);
            }
            if (lane < 24)   // 8 rows x 3 comps, contiguous in evec
                cpa4(EV + (rb8 + lane / 3) * 4 + (lane % 3),
                     evec + (size_t)(e0n + rb8) * 3 + lane);
            CP_COMMIT();
        }
        if (lane < 8 && t0 + (int)gridDim.x < NT) {
            sVn = __ldg(eidx + (t0 + gridDim.x) * 128 + rb8 + lane);
            dVn = __ldg(eidx + N_EDGES + (t0 + gridDim.x) * 128 + rb8 + lane);
        }
    }

    for (int t = t0; t < NT; t += gridDim.x) {
        CP_WAIT0();            // own cp.asyncs for tile t complete
        BARP(barid);           // pair done reading previous staging; partner cp.asyncs drained
        // ---- stage: SB -> MS/MX/MY/MZ (tf32) ----
        #pragma unroll
        for (int j = 0; j < 8; j++) {
            int row = rb8 + j;
            float4 st = *(const float4*)(SB + (row * 32 + lane) * 4);  // LDS.128, conflict-free
            MS[row * 36 + lane] = tf32f(st.x);
            MX[row * 36 + lane] = tf32f(st.y);
            MY[row * 36 + lane] = tf32f(st.z);
            MZ[row * 36 + lane] = tf32f(st.w);
        }
        // ---- SR: lane j<8 owns row rb8+j (holds its own dst in dV) ----
        if (lane < 8) {
            int row = rb8 + lane;
            float vx = EV[row * 4], vy = EV[row * 4 + 1], vz = EV[row * 4 + 2];
            float inv = rsqrtf(vx * vx + vy * vy + vz * vz);
            SR4[row] = make_float4(vx * inv, vy * inv, vz * inv, __int_as_float(dV));
        }
        // ---- SB/EV prefetch for t+1 (warp-private rows; no barrier needed) ----
        if (t + (int)gridDim.x < NT) {
            int e0n = (t + gridDim.x) * 128;
            #pragma unroll
            for (int j = 0; j < 8; j++) {
                int src = __shfl_sync(0xFFFFFFFFu, sVn, j);
                int row = rb8 + j;
                cpa16(SB + (row * 32 + lane) * 4, &g_state[src * 32 + lane]);
            }
            if (lane < 24)
                cpa4(EV + (rb8 + lane / 3) * 4 + (lane % 3),
                     evec + (size_t)(e0n + rb8) * 3 + lane);
            CP_COMMIT();
        }
        BARP(barid);           // staging + SR visible to pair

        // ---- phase 1: radial GEMM (reads EL) ----
        float Cr[8][4];
        #pragma unroll
        for (int i = 0; i < 8; i++) { Cr[i][0] = Cr[i][1] = Cr[i][2] = Cr[i][3] = 0.f; }
        #pragma unroll
        for (int k = 0; k < 7; k++) {
            int k0 = k << 3;
            const float* ab = EL + (r0 + g) * 60 + k0 + c;
            uint32_t a0 = __float_as_uint(ab[0]);
            uint32_t a1 = __float_as_uint(ab[8 * 60]);
            uint32_t a2 = __float_as_uint(ab[4]);
            uint32_t a3 = __float_as_uint(ab[8 * 60 + 4]);
            #pragma unroll
            for (int q = 0; q < 8; q++) {
                int ntg = ((q >> 1) << 2) + (p << 1) + (q & 1);
                const float* bb = RW + (k0 + c) * 136 + (ntg << 3) + g;
                uint32_t b0 = __float_as_uint(bb[0]);
                uint32_t b1 = __float_as_uint(bb[4 * 136]);
                MMA8(Cr[q], a0, a1, a2, a3, b0, b1);
            }
        }
        BARP(barid);           // pair done reading EL -> safe to refill

        // ---- EL prefetch for t+1 ----
        if (t + (int)gridDim.x < NT) {
            int e0n = (t + gridDim.x) * 128;
            #pragma unroll
            for (int j = 0; j < 8; j++) {
                int row = rb8 + j;
                size_t e = (size_t)(e0n + row);
                cpa4(EL + row * 60 + lane, elen + e * ESC + lane);
                if (lane < ESC - 32)
                    cpa4(EL + row * 60 + 32 + lane, elen + e * ESC + 32 + lane);
            }
            CP_COMMIT();
        }
        // rotate indices; preload for t+2 (hidden behind phase 2)
        dV = dVn;
        sVn = 0; dVn = 0;
        if (lane < 8 && t + 2 * (int)gridDim.x < NT) {
            sVn = __ldg(eidx + (t + 2 * gridDim.x) * 128 + rb8 + lane);
            dVn = __ldg(eidx + N_EDGES + (t + 2 * gridDim.x) * 128 + rb8 + lane);
        }

        // ---- phase 2: TP GEMMs + epilogue, per nt half (q = 0,1 -> nt = 2p+q) ----
        float4 rrl = SR4[r0 + g];
        float4 rrh = SR4[r0 + g + 8];
        #pragma unroll
        for (int q = 0; q < 2; q++) {
            int nt = (p << 1) + q;
            float cs1[4] = {0,0,0,0}, cs2[4] = {0,0,0,0};
            float cpx[4] = {0,0,0,0}, cpy[4] = {0,0,0,0}, cpz[4] = {0,0,0,0};
            float cax[4] = {0,0,0,0}, cay[4] = {0,0,0,0}, caz[4] = {0,0,0,0};
            #pragma unroll
            for (int k = 0; k < 4; k++) {
                int k0 = k << 3;
                const float* pp;
                pp = MS + (r0 + g) * 36 + k0 + c;
                uint32_t s0 = __float_as_uint(pp[0]), s1 = __float_as_uint(pp[8 * 36]);
                uint32_t s2 = __float_as_uint(pp[4]), s3 = __float_as_uint(pp[8 * 36 + 4]);
                pp = MX + (r0 + g) * 36 + k0 + c;
                uint32_t x0 = __float_as_uint(pp[0]), x1 = __float_as_uint(pp[8 * 36]);
                uint32_t x2 = __float_as_uint(pp[4]), x3 = __float_as_uint(pp[8 * 36 + 4]);
                pp = MY + (r0 + g) * 36 + k0 + c;
                uint32_t y0 = __float_as_uint(pp[0]), y1 = __float_as_uint(pp[8 * 36]);
                uint32_t y2 = __float_as_uint(pp[4]), y3 = __float_as_uint(pp[8 * 36 + 4]);
                pp = MZ + (r0 + g) * 36 + k0 + c;
                uint32_t z0 = __float_as_uint(pp[0]), z1 = __float_as_uint(pp[8 * 36]);
                uint32_t z2 = __float_as_uint(pp[4]), z3 = __float_as_uint(pp[8 * 36 + 4]);

                const float* bb = BC + (k0 + c) * 72 + (nt << 3) + g;
                uint32_t bc10 = __float_as_uint(bb[0]), bc11 = __float_as_uint(bb[4 * 72]);
                uint32_t bc20 = __float_as_uint(bb[32]), bc21 = __float_as_uint(bb[4 * 72 + 32]);
                bb = VS + (k0 + c) * 40 + (nt << 3) + g;
                uint32_t vs0 = __float_as_uint(bb[0]), vs1 = __float_as_uint(bb[4 * 40]);
                bb = VV + (k0 + c) * 40 + (nt << 3) + g;
                uint32_t vv0 = __float_as_uint(bb[0]), vv1 = __float_as_uint(bb[4 * 40]);

                MMA8(cs1, s0, s1, s2, s3, bc10, bc11);
                MMA8(cs2, s0, s1, s2, s3, bc20, bc21);
                MMA8(cpx, x0, x1, x2, x3, vs0, vs1);
                MMA8(cpy, y0, y1, y2, y3, vs0, vs1);
                MMA8(cpz, z0, z1, z2, z3, vs0, vs1);
                MMA8(cax, x0, x1, x2, x3, vv0, vv1);
                MMA8(cay, y0, y1, y2, y3, vv0, vv1);
                MMA8(caz, z0, z1, z2, z3, vv0, vv1);
            }
            #pragma unroll
            for (int h = 0; h < 2; h++) {
                float4 rr = h ? rrh : rrl;
                int dst = __float_as_int(rr.w);
                float Yx = SQRT3F * rr.x, Yy = SQRT3F * rr.y, Yz = SQRT3F * rr.z;
                #pragma unroll
                for (int u = 0; u < 2; u++) {
                    int idx = (h << 1) + u;
                    int ch = (nt << 3) + 2 * c + u;
                    float gs = sigmoidf_(Cr[q][idx]     + rbv[0][q][u]);
                    float gx = sigmoidf_(Cr[2 + q][idx] + rbv[1][q][u]);
                    float gy = sigmoidf_(Cr[4 + q][idx] + rbv[2][q][u]);
                    float gz = sigmoidf_(Cr[6 + q][idx] + rbv[3][q][u]);
                    float sOut = (cs1[idx] + rr.x * cpx[idx] + rr.y * cpy[idx]
                                + rr.z * cpz[idx]) * TP_NORM * gs;
                    float sv = cs2[idx];
                    float ovx = (sv * Yx + cax[idx]) * TP_NORM * gx;
                    float ovy = (sv * Yy + cay[idx]) * TP_NORM * gy;
                    float ovz = (sv * Yz + caz[idx]) * TP_NORM * gz;
                    float4* ap = &g_agg[dst * 32 + ch];
                    asm volatile("red.global.add.v4.f32 [%0], {%1,%2,%3,%4};"
                        :: "l"(ap), "f"(sOut), "f"(ovx), "f"(ovy), "f"(ovz) : "memory");
                }
            }
        }
    }
}

__global__ void k_node(const float* __restrict__ Ls, const float* __restrict__ Lv,
                       int stage,
                       const float* __restrict__ lng, const float* __restrict__ lnb,
                       const float* __restrict__ Gw, const float* __restrict__ Gb)
{
    __shared__ float sS[4][32];
    __shared__ float sV[4][3][32];
    int w = threadIdx.x >> 5, lane = threadIdx.x & 31;
    int n = blockIdx.x * 4 + w;
    if (n >= N_NODES) return;

    float4 ag = g_agg[n * 32 + lane];
    g_agg[n * 32 + lane] = make_float4(0.f, 0.f, 0.f, 0.f);
    float4 st = g_state[n * 32 + lane];
    sS[w][lane] = st.x + ag.x;
    sV[w][0][lane] = st.y + ag.y;
    sV[w][1][lane] = st.z + ag.z;
    sV[w][2][lane] = st.w + ag.w;
    __syncwarp();

    float ns = 0.0f, nvx = 0.0f, nvy = 0.0f, nvz = 0.0f;
    #pragma unroll 8
    for (int i = 0; i < 32; i++) {
        int o = i * 32 + lane;
        ns += sS[w][i] * __ldg(Ls + o);
        float lw = __ldg(Lv + o);
        nvx += sV[w][0][i] * lw; nvy += sV[w][1][i] * lw; nvz += sV[w][2][i] * lw;
    }
    ns *= INV_SQRT32; nvx *= INV_SQRT32; nvy *= INV_SQRT32; nvz *= INV_SQRT32;
    __syncwarp();
    warp_process(ns, nvx, nvy, nvz, lane, sS[w], stage, lng, lnb, Gw, Gb);
    g_state[n * 32 + lane] = make_float4(ns, nvx, nvy, nvz);
}

__global__ void k_out(const float* __restrict__ Os, const float* __restrict__ Ov,
                      const float* __restrict__ lng, const float* __restrict__ lnb,
                      const float* __restrict__ Gw, const float* __restrict__ Gb,
                      const float* __restrict__ Psw, const float* __restrict__ Psb,
                      const float* __restrict__ Pvw, const float* __restrict__ Pvb,
                      float* __restrict__ out)
{
    __shared__ float sS[4][32];
    __shared__ float sV[4][3][32];
    int w = threadIdx.x >> 5, lane = threadIdx.x & 31;
    int n = blockIdx.x * 4 + w;
    if (n >= N_NODES) return;

    float4 st = g_state[n * 32 + lane];
    sS[w][lane] = st.x;
    sV[w][0][lane] = st.y;
    sV[w][1][lane] = st.z;
    sV[w][2][lane] = st.w;
    __syncwarp();

    float ns = 0.0f, nvx = 0.0f, nvy = 0.0f, nvz = 0.0f;
    #pragma unroll 8
    for (int i = 0; i < 32; i++) {
        int o = i * 32 + lane;
        ns += sS[w][i] * __ldg(Os + o);
        float lw = __ldg(Ov + o);
        nvx += sV[w][0][i] * lw; nvy += sV[w][1][i] * lw; nvz += sV[w][2][i] * lw;
    }
    ns *= INV_SQRT32; nvx *= INV_SQRT32; nvy *= INV_SQRT32; nvz *= INV_SQRT32;
    __syncwarp();
    warp_process(ns, nvx, nvy, nvz, lane, sS[w], 3, lng, lnb, Gw, Gb);
    __syncwarp();
    sV[w][0][lane] = nvx; sV[w][1][lane] = nvy; sV[w][2][lane] = nvz;
    __syncwarp();

    float sc0 = 0.f, sc1 = 0.f, t00 = 0.f, t01 = 0.f, t10 = 0.f, t11 = 0.f, t20 = 0.f, t21 = 0.f;
    #pragma unroll 8
    for (int i = 0; i < 32; i++) {
        float si = sS[w][i];
        float vx = sV[w][0][i], vy = sV[w][1][i], vz = sV[w][2][i];
        float pw0 = __ldg(Psw + i * 64 + lane), pw1 = __ldg(Psw + i * 64 + 32 + lane);
        float qw0 = __ldg(Pvw + i * 64 + lane), qw1 = __ldg(Pvw + i * 64 + 32 + lane);
        sc0 += si * pw0; sc1 += si * pw1;
        t00 += vx * qw0; t01 += vx * qw1;
        t10 += vy * qw0; t11 += vy * qw1;
        t20 += vz * qw0; t21 += vz * qw1;
    }
    float base0 = sc0 + __ldg(Psb + lane) + __ldg(Pvb + lane);
    float base1 = sc1 + __ldg(Psb + 32 + lane) + __ldg(Pvb + 32 + lane);
    size_t ob = (size_t)n * 192;
    out[ob + lane]       = t00 + base0;
    out[ob + 32 + lane]  = t01 + base1;
    out[ob + 64 + lane]  = t10 + base0;
    out[ob + 96 + lane]  = t11 + base1;
    out[ob + 128 + lane] = t20 + base0;
    out[ob + 160 + lane] = t21 + base1;
}

extern "C" void kernel_launch(void* const* d_in, const int* in_sizes, int n_in,
                              void* d_out, int out_size)
{
    const float* x    = (const float*)d_in[0];
    const float* deg  = (const float*)d_in[1];
    const float* pos  = (const float*)d_in[2];
    const float* evec = (const float*)d_in[3];
    const float* elen = (const float*)d_in[4];
    const int*   eidx = (const int*)d_in[5];
    const float* Wes  = (const float*)d_in[6];
    const float* Wev  = (const float*)d_in[7];
    const float* Wss  = (const float*)d_in[8];
    const float* Wvs  = (const float*)d_in[9];
    const float* Wsv  = (const float*)d_in[10];
    const float* Wvv  = (const float*)d_in[11];
    const float* Ls   = (const float*)d_in[12];
    const float* Lv   = (const float*)d_in[13];
    const float* Rw   = (const float*)d_in[14];
    const float* Rb   = (const float*)d_in[15];
    const float* lng  = (const float*)d_in[16];
    const float* lnb  = (const float*)d_in[17];
    const float* Gw   = (const float*)d_in[18];
    const float* Gb   = (const float*)d_in[19];
    const float* Os   = (const float*)d_in[20];
    const float* Ov   = (const float*)d_in[21];
    const float* Psw  = (const float*)d_in[22];
    const float* Psb  = (const float*)d_in[23];
    const float* Pvw  = (const float*)d_in[24];
    const float* Pvb  = (const float*)d_in[25];
    float* out = (float*)d_out;

    static int smem_set = 0;
    if (!smem_set) {
        cudaFuncSetAttribute(k_edge, cudaFuncAttributeMaxDynamicSharedMemorySize, SMEM_BYTES);
        smem_set = 1;
    }

    int node_blocks = (N_NODES + 3) / 4;
    k_embed<<<node_blocks, 128>>>(x, deg, pos, Wes, Wev, lng, lnb, Gw, Gb);
    for (int l = 0; l < 2; l++) {
        k_edge<<<148, 512, SMEM_BYTES>>>(eidx, evec, elen,
                                         Wss + l * 1024, Wvs + l * 1024,
                                         Wsv + l * 1024, Wvv + l * 1024,
                                         Rw + l * ESC * 128, Rb + l * 128);
        k_node<<<node_blocks, 128>>>(Ls + l * 1024, Lv + l * 1024, l + 1, lng, lnb, Gw, Gb);
    }
    k_out<<<node_blocks, 128>>>(Os, Ov, lng, lnb, Gw, Gb, Psw, Psb, Pvw, Pvb, out);
}

// round 16
// speedup vs baseline: 1.4195x; 1.0155x over previous
#include <cuda_runtime.h>
#include <cstdint>
#include <math.h>

#define N_NODES 50000
#define N_EDGES 800000
#define ESC 50
#define SQRT3F 1.7320508075688772f
#define TP_NORM 0.125f
#define INV_SQRT32 0.17677669529663687f
#define INV_SQRT119 0.09166984970282113f
#define NT 6250

// smem offsets (floats)
#define O_MS 0
#define O_MX 4608
#define O_MY 9216
#define O_MZ 13824
#define O_EL 18432
#define O_BC 26112
#define O_VS 28416
#define O_VV 29696
#define O_RW 30976
#define O_SR 38592
#define O_SB 39104
#define O_EV 55488
#define SMEM_FLOATS 56000
#define SMEM_BYTES (SMEM_FLOATS * 4)

__device__ float4 g_state[N_NODES * 32];  // {s, vx, vy, vz} per (node, channel)
__device__ float4 g_agg[N_NODES * 32];    // {s, vx, vy, vz}

__device__ __forceinline__ float sigmoidf_(float x) { return 1.0f / (1.0f + __expf(-x)); }
__device__ __forceinline__ float warp_sum(float v) {
    #pragma unroll
    for (int o = 16; o > 0; o >>= 1) v += __shfl_xor_sync(0xFFFFFFFFu, v, o);
    return v;
}
__device__ __forceinline__ float tf32f(float f) {
    uint32_t r; asm("cvt.rna.tf32.f32 %0, %1;" : "=r"(r) : "f"(f));
    return __uint_as_float(r);
}
__device__ __forceinline__ void cpa4(float* smem_dst, const float* gsrc) {
    uint32_t a = (uint32_t)__cvta_generic_to_shared(smem_dst);
    asm volatile("cp.async.ca.shared.global [%0], [%1], 4;" :: "r"(a), "l"(gsrc));
}
__device__ __forceinline__ void cpa16(float* smem_dst, const float4* gsrc) {
    uint32_t a = (uint32_t)__cvta_generic_to_shared(smem_dst);
    asm volatile("cp.async.cg.shared.global [%0], [%1], 16;" :: "r"(a), "l"(gsrc));
}
#define CP_COMMIT() asm volatile("cp.async.commit_group;" ::: "memory")
#define CP_WAIT0()  asm volatile("cp.async.wait_group 0;" ::: "memory")

#define MMA8(D, a0, a1, a2, a3, b0, b1) \
    asm volatile("mma.sync.aligned.m16n8k8.row.col.f32.tf32.tf32.f32 " \
        "{%0,%1,%2,%3}, {%4,%5,%6,%7}, {%8,%9}, {%0,%1,%2,%3};" \
        : "+f"((D)[0]), "+f"((D)[1]), "+f"((D)[2]), "+f"((D)[3]) \
        : "r"(a0), "r"(a1), "r"(a2), "r"(a3), "r"(b0), "r"(b1))

#define BARP(id) asm volatile("bar.sync %0, %1;" :: "r"(id), "r"(64) : "memory")

// ---------------- node embedding: 8 nodes per warp, weights amortized ----------------
__global__ void k_embed(const float* __restrict__ x, const float* __restrict__ deg,
                        const float* __restrict__ pos,
                        const float* __restrict__ Wes, const float* __restrict__ Wev,
                        const float* __restrict__ lng, const float* __restrict__ lnb,
                        const float* __restrict__ Gw, const float* __restrict__ Gb)
{
    __shared__ float stage[4][8][32];
    int w = threadIdx.x >> 5, lane = threadIdx.x & 31;
    int nb = (blockIdx.x * 4 + w) * 8;
    if (nb >= N_NODES) return;

    float acc[8];
    #pragma unroll
    for (int n = 0; n < 8; n++) acc[n] = 0.f;
    for (int i = 0; i < 59; i++) {
        float w0 = __ldg(Wes + (2 * i) * 32 + lane);
        float w1 = __ldg(Wes + (2 * i + 1) * 32 + lane);
        #pragma unroll
        for (int n = 0; n < 8; n++) {
            float2 v = __ldg((const float2*)(x + (size_t)(nb + n) * 118) + i);
            acc[n] += v.x * w0 + v.y * w1;
        }
    }
    float wd = __ldg(Wes + 118 * 32 + lane);
    float lg = __ldg(lng + lane), lb = __ldg(lnb + lane);
    #pragma unroll
    for (int n = 0; n < 8; n++) {
        float s = (acc[n] + __ldg(deg + nb + n) * wd) * INV_SQRT119;
        float m = warp_sum(s) * (1.0f / 32.0f);
        float d = s - m;
        float var = warp_sum(d * d) * (1.0f / 32.0f);
        float sn = d * rsqrtf(var + 1e-5f) * lg + lb;
        float a = sn * sigmoidf_(sn);
        stage[w][n][lane] = a;
        acc[n] = a;
    }
    __syncwarp();
    float gacc[8];
    float gb = __ldg(Gb + lane);
    #pragma unroll
    for (int n = 0; n < 8; n++) gacc[n] = gb;
    #pragma unroll 8
    for (int i = 0; i < 32; i++) {
        float gw_i = __ldg(Gw + i * 32 + lane);
        #pragma unroll
        for (int n = 0; n < 8; n++) gacc[n] += stage[w][n][i] * gw_i;
    }
    float wv = __ldg(Wev + lane);
    #pragma unroll
    for (int n = 0; n < 8; n++) {
        int nn = nb + n;
        float mg = wv * sigmoidf_(gacc[n]);
        float px = __ldg(pos + nn * 3 + 0), py = __ldg(pos + nn * 3 + 1), pz = __ldg(pos + nn * 3 + 2);
        g_state[nn * 32 + lane] = make_float4(acc[n], px * mg, py * mg, pz * mg);
        g_agg[nn * 32 + lane] = make_float4(0.f, 0.f, 0.f, 0.f);
    }
}

// ---------------- fused edge kernel (R15, unchanged) ----------------
__global__ void __launch_bounds__(512, 1) k_edge(
    const int* __restrict__ eidx, const float* __restrict__ evec,
    const float* __restrict__ elen,
    const float* __restrict__ Wss, const float* __restrict__ Wvs,
    const float* __restrict__ Wsv, const float* __restrict__ Wvv,
    const float* __restrict__ Rw, const float* __restrict__ Rb)
{
    extern __shared__ float sm[];
    float* MS = sm + O_MS;
    float* MX = sm + O_MX;
    float* MY = sm + O_MY;
    float* MZ = sm + O_MZ;
    float* EL = sm + O_EL;
    float* BC = sm + O_BC;
    float* VS = sm + O_VS;
    float* VV = sm + O_VV;
    float* RW = sm + O_RW;
    float4* SR4 = (float4*)(sm + O_SR);
    float* SB = sm + O_SB;
    float* EV = sm + O_EV;

    int tid = threadIdx.x, w = tid >> 5, lane = tid & 31;
    int pair = w >> 1, p = w & 1;
    int g = lane >> 2, c = lane & 3;
    int r0 = pair << 4;
    int rb8 = r0 + (p << 3);
    int barid = 8 + pair;

    for (int i = tid; i < 56 * 136; i += 512) {
        int k = i / 136, n = i % 136;
        float v = 0.f;
        if (k < ESC && n < 128) {
            int ch = n & 31, m = n >> 5;
            int col = (m == 0) ? ch : 32 + 3 * ch + (m - 1);
            v = __ldg(Rw + k * 128 + col);
        }
        RW[i] = tf32f(v);
    }
    for (int i = tid; i < 32 * 72; i += 512) {
        int k = i / 72, n = i % 72;
        float v = (n < 32) ? __ldg(Wss + k * 32 + n) : ((n < 64) ? __ldg(Wsv + k * 32 + n - 32) : 0.f);
        BC[i] = tf32f(v);
    }
    for (int i = tid; i < 32 * 40; i += 512) {
        int k = i / 40, n = i % 40;
        VS[i] = (n < 32) ? tf32f(__ldg(Wvs + k * 32 + n)) : 0.f;
        VV[i] = (n < 32) ? tf32f(__ldg(Wvv + k * 32 + n)) : 0.f;
    }
    for (int i = tid; i < 128 * 10; i += 512)
        EL[(i / 10) * 60 + 50 + (i % 10)] = 0.f;
    __syncthreads();

    float rbv[4][2][2];
    #pragma unroll
    for (int m = 0; m < 4; m++)
        #pragma unroll
        for (int qq = 0; qq < 2; qq++)
            #pragma unroll
            for (int u = 0; u < 2; u++) {
                int ch = 16 * p + 8 * qq + 2 * c + u;
                int col = (m == 0) ? ch : 32 + 3 * ch + (m - 1);
                rbv[m][qq][u] = __ldg(Rb + col);
            }

    int dV = 0, sVn = 0, dVn = 0;

    int t0 = blockIdx.x;
    {
        int sV0 = 0;
        if (lane < 8 && t0 < NT) {
            sV0 = __ldg(eidx + t0 * 128 + rb8 + lane);
            dV  = __ldg(eidx + N_EDGES + t0 * 128 + rb8 + lane);
        }
        if (t0 < NT) {
            int e0n = t0 * 128;
            #pragma unroll
            for (int j = 0; j < 8; j++) {
                int src = __shfl_sync(0xFFFFFFFFu, sV0, j);
                int row = rb8 + j;
                size_t e = (size_t)(e0n + row);
                cpa16(SB + (row * 32 + lane) * 4, &g_state[src * 32 + lane]);
                cpa4(EL + row * 60 + lane, elen + e * ESC + lane);
                if (lane < ESC - 32)
                    cpa4(EL + row * 60 + 32 + lane, elen + e * ESC + 32 + lane);
            }
            if (lane < 24)
                cpa4(EV + (rb8 + lane / 3) * 4 + (lane % 3),
                     evec + (size_t)(e0n + rb8) * 3 + lane);
            CP_COMMIT();
        }
        if (lane < 8 && t0 + (int)gridDim.x < NT) {
            sVn = __ldg(eidx + (t0 + gridDim.x) * 128 + rb8 + lane);
            dVn = __ldg(eidx + N_EDGES + (t0 + gridDim.x) * 128 + rb8 + lane);
        }
    }

    for (int t = t0; t < NT; t += gridDim.x) {
        CP_WAIT0();
        BARP(barid);
        #pragma unroll
        for (int j = 0; j < 8; j++) {
            int row = rb8 + j;
            float4 st = *(const float4*)(SB + (row * 32 + lane) * 4);
            MS[row * 36 + lane] = tf32f(st.x);
            MX[row * 36 + lane] = tf32f(st.y);
            MY[row * 36 + lane] = tf32f(st.z);
            MZ[row * 36 + lane] = tf32f(st.w);
        }
        if (lane < 8) {
            int row = rb8 + lane;
            float vx = EV[row * 4], vy = EV[row * 4 + 1], vz = EV[row * 4 + 2];
            float inv = rsqrtf(vx * vx + vy * vy + vz * vz);
            SR4[row] = make_float4(vx * inv, vy * inv, vz * inv, __int_as_float(dV));
        }
        if (t + (int)gridDim.x < NT) {
            int e0n = (t + gridDim.x) * 128;
            #pragma unroll
            for (int j = 0; j < 8; j++) {
                int src = __shfl_sync(0xFFFFFFFFu, sVn, j);
                int row = rb8 + j;
                cpa16(SB + (row * 32 + lane) * 4, &g_state[src * 32 + lane]);
            }
            if (lane < 24)
                cpa4(EV + (rb8 + lane / 3) * 4 + (lane % 3),
                     evec + (size_t)(e0n + rb8) * 3 + lane);
            CP_COMMIT();
        }
        BARP(barid);

        float Cr[8][4];
        #pragma unroll
        for (int i = 0; i < 8; i++) { Cr[i][0] = Cr[i][1] = Cr[i][2] = Cr[i][3] = 0.f; }
        #pragma unroll
        for (int k = 0; k < 7; k++) {
            int k0 = k << 3;
            const float* ab = EL + (r0 + g) * 60 + k0 + c;
            uint32_t a0 = __float_as_uint(ab[0]);
            uint32_t a1 = __float_as_uint(ab[8 * 60]);
            uint32_t a2 = __float_as_uint(ab[4]);
            uint32_t a3 = __float_as_uint(ab[8 * 60 + 4]);
            #pragma unroll
            for (int q = 0; q < 8; q++) {
                int ntg = ((q >> 1) << 2) + (p << 1) + (q & 1);
                const float* bb = RW + (k0 + c) * 136 + (ntg << 3) + g;
                uint32_t b0 = __float_as_uint(bb[0]);
                uint32_t b1 = __float_as_uint(bb[4 * 136]);
                MMA8(Cr[q], a0, a1, a2, a3, b0, b1);
            }
        }
        BARP(barid);

        if (t + (int)gridDim.x < NT) {
            int e0n = (t + gridDim.x) * 128;
            #pragma unroll
            for (int j = 0; j < 8; j++) {
                int row = rb8 + j;
                size_t e = (size_t)(e0n + row);
                cpa4(EL + row * 60 + lane, elen + e * ESC + lane);
                if (lane < ESC - 32)
                    cpa4(EL + row * 60 + 32 + lane, elen + e * ESC + 32 + lane);
            }
            CP_COMMIT();
        }
        dV = dVn;
        sVn = 0; dVn = 0;
        if (lane < 8 && t + 2 * (int)gridDim.x < NT) {
            sVn = __ldg(eidx + (t + 2 * gridDim.x) * 128 + rb8 + lane);
            dVn = __ldg(eidx + N_EDGES + (t + 2 * gridDim.x) * 128 + rb8 + lane);
        }

        float4 rrl = SR4[r0 + g];
        float4 rrh = SR4[r0 + g + 8];
        #pragma unroll
        for (int q = 0; q < 2; q++) {
            int nt = (p << 1) + q;
            float cs1[4] = {0,0,0,0}, cs2[4] = {0,0,0,0};
            float cpx[4] = {0,0,0,0}, cpy[4] = {0,0,0,0}, cpz[4] = {0,0,0,0};
            float cax[4] = {0,0,0,0}, cay[4] = {0,0,0,0}, caz[4] = {0,0,0,0};
            #pragma unroll
            for (int k = 0; k < 4; k++) {
                int k0 = k << 3;
                const float* pp;
                pp = MS + (r0 + g) * 36 + k0 + c;
                uint32_t s0 = __float_as_uint(pp[0]), s1 = __float_as_uint(pp[8 * 36]);
                uint32_t s2 = __float_as_uint(pp[4]), s3 = __float_as_uint(pp[8 * 36 + 4]);
                pp = MX + (r0 + g) * 36 + k0 + c;
                uint32_t x0 = __float_as_uint(pp[0]), x1 = __float_as_uint(pp[8 * 36]);
                uint32_t x2 = __float_as_uint(pp[4]), x3 = __float_as_uint(pp[8 * 36 + 4]);
                pp = MY + (r0 + g) * 36 + k0 + c;
                uint32_t y0 = __float_as_uint(pp[0]), y1 = __float_as_uint(pp[8 * 36]);
                uint32_t y2 = __float_as_uint(pp[4]), y3 = __float_as_uint(pp[8 * 36 + 4]);
                pp = MZ + (r0 + g) * 36 + k0 + c;
                uint32_t z0 = __float_as_uint(pp[0]), z1 = __float_as_uint(pp[8 * 36]);
                uint32_t z2 = __float_as_uint(pp[4]), z3 = __float_as_uint(pp[8 * 36 + 4]);

                const float* bb = BC + (k0 + c) * 72 + (nt << 3) + g;
                uint32_t bc10 = __float_as_uint(bb[0]), bc11 = __float_as_uint(bb[4 * 72]);
                uint32_t bc20 = __float_as_uint(bb[32]), bc21 = __float_as_uint(bb[4 * 72 + 32]);
                bb = VS + (k0 + c) * 40 + (nt << 3) + g;
                uint32_t vs0 = __float_as_uint(bb[0]), vs1 = __float_as_uint(bb[4 * 40]);
                bb = VV + (k0 + c) * 40 + (nt << 3) + g;
                uint32_t vv0 = __float_as_uint(bb[0]), vv1 = __float_as_uint(bb[4 * 40]);

                MMA8(cs1, s0, s1, s2, s3, bc10, bc11);
                MMA8(cs2, s0, s1, s2, s3, bc20, bc21);
                MMA8(cpx, x0, x1, x2, x3, vs0, vs1);
                MMA8(cpy, y0, y1, y2, y3, vs0, vs1);
                MMA8(cpz, z0, z1, z2, z3, vs0, vs1);
                MMA8(cax, x0, x1, x2, x3, vv0, vv1);
                MMA8(cay, y0, y1, y2, y3, vv0, vv1);
                MMA8(caz, z0, z1, z2, z3, vv0, vv1);
            }
            #pragma unroll
            for (int h = 0; h < 2; h++) {
                float4 rr = h ? rrh : rrl;
                int dst = __float_as_int(rr.w);
                float Yx = SQRT3F * rr.x, Yy = SQRT3F * rr.y, Yz = SQRT3F * rr.z;
                #pragma unroll
                for (int u = 0; u < 2; u++) {
                    int idx = (h << 1) + u;
                    int ch = (nt << 3) + 2 * c + u;
                    float gs = sigmoidf_(Cr[q][idx]     + rbv[0][q][u]);
                    float gx = sigmoidf_(Cr[2 + q][idx] + rbv[1][q][u]);
                    float gy = sigmoidf_(Cr[4 + q][idx] + rbv[2][q][u]);
                    float gz = sigmoidf_(Cr[6 + q][idx] + rbv[3][q][u]);
                    float sOut = (cs1[idx] + rr.x * cpx[idx] + rr.y * cpy[idx]
                                + rr.z * cpz[idx]) * TP_NORM * gs;
                    float sv = cs2[idx];
                    float ovx = (sv * Yx + cax[idx]) * TP_NORM * gx;
                    float ovy = (sv * Yy + cay[idx]) * TP_NORM * gy;
                    float ovz = (sv * Yz + caz[idx]) * TP_NORM * gz;
                    float4* ap = &g_agg[dst * 32 + ch];
                    asm volatile("red.global.add.v4.f32 [%0], {%1,%2,%3,%4};"
                        :: "l"(ap), "f"(sOut), "f"(ovx), "f"(ovy), "f"(ovz) : "memory");
                }
            }
        }
    }
}

// ---------------- node update: 4 nodes per warp, weights amortized ----------------
__global__ void k_node(const float* __restrict__ Ls, const float* __restrict__ Lv,
                       int stage,
                       const float* __restrict__ lng, const float* __restrict__ lnb,
                       const float* __restrict__ Gw, const float* __restrict__ Gb)
{
    __shared__ float sS[4][4][32], sVx[4][4][32], sVy[4][4][32], sVz[4][4][32];
    int w = threadIdx.x >> 5, lane = threadIdx.x & 31;
    int nb = (blockIdx.x * 4 + w) * 4;   // 50000 = 3125 blocks * 16, exact

    #pragma unroll
    for (int n = 0; n < 4; n++) {
        int nn = nb + n;
        float4 ag = g_agg[nn * 32 + lane];
        g_agg[nn * 32 + lane] = make_float4(0.f, 0.f, 0.f, 0.f);
        float4 st = g_state[nn * 32 + lane];
        sS[w][n][lane] = st.x + ag.x;
        sVx[w][n][lane] = st.y + ag.y;
        sVy[w][n][lane] = st.z + ag.z;
        sVz[w][n][lane] = st.w + ag.w;
    }
    __syncwarp();

    float ns[4] = {0,0,0,0}, nx[4] = {0,0,0,0}, ny[4] = {0,0,0,0}, nz[4] = {0,0,0,0};
    #pragma unroll 8
    for (int i = 0; i < 32; i++) {
        float ls = __ldg(Ls + i * 32 + lane);
        float lv = __ldg(Lv + i * 32 + lane);
        #pragma unroll
        for (int n = 0; n < 4; n++) {
            ns[n] += sS[w][n][i] * ls;
            nx[n] += sVx[w][n][i] * lv;
            ny[n] += sVy[w][n][i] * lv;
            nz[n] += sVz[w][n][i] * lv;
        }
    }
    __syncwarp();

    float lg = __ldg(lng + stage * 32 + lane), lb = __ldg(lnb + stage * 32 + lane);
    #pragma unroll
    for (int n = 0; n < 4; n++) {
        float s = ns[n] * INV_SQRT32;
        float m = warp_sum(s) * (1.0f / 32.0f);
        float d = s - m;
        float var = warp_sum(d * d) * (1.0f / 32.0f);
        float sn = d * rsqrtf(var + 1e-5f) * lg + lb;
        float a = sn * sigmoidf_(sn);
        sS[w][n][lane] = a;
        ns[n] = a;
    }
    __syncwarp();
    float gacc[4];
    float gb = __ldg(Gb + stage * 32 + lane);
    #pragma unroll
    for (int n = 0; n < 4; n++) gacc[n] = gb;
    const float* gw = Gw + stage * 1024;
    #pragma unroll 8
    for (int i = 0; i < 32; i++) {
        float gw_i = __ldg(gw + i * 32 + lane);
        #pragma unroll
        for (int n = 0; n < 4; n++) gacc[n] += sS[w][n][i] * gw_i;
    }
    #pragma unroll
    for (int n = 0; n < 4; n++) {
        float g = sigmoidf_(gacc[n]) * INV_SQRT32;
        g_state[(nb + n) * 32 + lane] = make_float4(ns[n], nx[n] * g, ny[n] * g, nz[n] * g);
    }
}

// ---------------- output head: 4 nodes per warp, weights amortized ----------------
__global__ void k_out(const float* __restrict__ Os, const float* __restrict__ Ov,
                      const float* __restrict__ lng, const float* __restrict__ lnb,
                      const float* __restrict__ Gw, const float* __restrict__ Gb,
                      const float* __restrict__ Psw, const float* __restrict__ Psb,
                      const float* __restrict__ Pvw, const float* __restrict__ Pvb,
                      float* __restrict__ out)
{
    __shared__ float sS[4][4][32], sVx[4][4][32], sVy[4][4][32], sVz[4][4][32];
    int w = threadIdx.x >> 5, lane = threadIdx.x & 31;
    int nb = (blockIdx.x * 4 + w) * 4;

    #pragma unroll
    for (int n = 0; n < 4; n++) {
        float4 st = g_state[(nb + n) * 32 + lane];
        sS[w][n][lane] = st.x;
        sVx[w][n][lane] = st.y;
        sVy[w][n][lane] = st.z;
        sVz[w][n][lane] = st.w;
    }
    __syncwarp();

    float ns[4] = {0,0,0,0}, nx[4] = {0,0,0,0}, ny[4] = {0,0,0,0}, nz[4] = {0,0,0,0};
    #pragma unroll 8
    for (int i = 0; i < 32; i++) {
        float os = __ldg(Os + i * 32 + lane);
        float ov = __ldg(Ov + i * 32 + lane);
        #pragma unroll
        for (int n = 0; n < 4; n++) {
            ns[n] += sS[w][n][i] * os;
            nx[n] += sVx[w][n][i] * ov;
            ny[n] += sVy[w][n][i] * ov;
            nz[n] += sVz[w][n][i] * ov;
        }
    }
    __syncwarp();

    float lg = __ldg(lng + 96 + lane), lb = __ldg(lnb + 96 + lane);   // stage 3
    #pragma unroll
    for (int n = 0; n < 4; n++) {
        float s = ns[n] * INV_SQRT32;
        float m = warp_sum(s) * (1.0f / 32.0f);
        float d = s - m;
        float var = warp_sum(d * d) * (1.0f / 32.0f);
        float sn = d * rsqrtf(var + 1e-5f) * lg + lb;
        float a = sn * sigmoidf_(sn);
        sS[w][n][lane] = a;
    }
    __syncwarp();
    float gacc[4];
    float gb = __ldg(Gb + 96 + lane);
    #pragma unroll
    for (int n = 0; n < 4; n++) gacc[n] = gb;
    const float* gw = Gw + 3 * 1024;
    #pragma unroll 8
    for (int i = 0; i < 32; i++) {
        float gw_i = __ldg(gw + i * 32 + lane);
        #pragma unroll
        for (int n = 0; n < 4; n++) gacc[n] += sS[w][n][i] * gw_i;
    }
    #pragma unroll
    for (int n = 0; n < 4; n++) {
        float g = sigmoidf_(gacc[n]) * INV_SQRT32;
        sVx[w][n][lane] = nx[n] * g;
        sVy[w][n][lane] = ny[n] * g;
        sVz[w][n][lane] = nz[n] * g;
    }
    __syncwarp();

    // projections: per-node accumulators, weights shared across 4 nodes
    float sc0[4] = {0,0,0,0}, sc1[4] = {0,0,0,0};
    float t00[4] = {0,0,0,0}, t01[4] = {0,0,0,0};
    float t10[4] = {0,0,0,0}, t11[4] = {0,0,0,0};
    float t20[4] = {0,0,0,0}, t21[4] = {0,0,0,0};
    #pragma unroll 4
    for (int i = 0; i < 32; i++) {
        float pw0 = __ldg(Psw + i * 64 + lane), pw1 = __ldg(Psw + i * 64 + 32 + lane);
        float qw0 = __ldg(Pvw + i * 64 + lane), qw1 = __ldg(Pvw + i * 64 + 32 + lane);
        #pragma unroll
        for (int n = 0; n < 4; n++) {
            float si = sS[w][n][i];
            float vx = sVx[w][n][i], vy = sVy[w][n][i], vz = sVz[w][n][i];
            sc0[n] += si * pw0; sc1[n] += si * pw1;
            t00[n] += vx * qw0; t01[n] += vx * qw1;
            t10[n] += vy * qw0; t11[n] += vy * qw1;
            t20[n] += vz * qw0; t21[n] += vz * qw1;
        }
    }
    float pb0 = __ldg(Psb + lane) + __ldg(Pvb + lane);
    float pb1 = __ldg(Psb + 32 + lane) + __ldg(Pvb + 32 + lane);
    #pragma unroll
    for (int n = 0; n < 4; n++) {
        float base0 = sc0[n] + pb0;
        float base1 = sc1[n] + pb1;
        size_t ob = (size_t)(nb + n) * 192;
        out[ob + lane]       = t00[n] + base0;
        out[ob + 32 + lane]  = t01[n] + base1;
        out[ob + 64 + lane]  = t10[n] + base0;
        out[ob + 96 + lane]  = t11[n] + base1;
        out[ob + 128 + lane] = t20[n] + base0;
        out[ob + 160 + lane] = t21[n] + base1;
    }
}

extern "C" void kernel_launch(void* const* d_in, const int* in_sizes, int n_in,
                              void* d_out, int out_size)
{
    const float* x    = (const float*)d_in[0];
    const float* deg  = (const float*)d_in[1];
    const float* pos  = (const float*)d_in[2];
    const float* evec = (const float*)d_in[3];
    const float* elen = (const float*)d_in[4];
    const int*   eidx = (const int*)d_in[5];
    const float* Wes  = (const float*)d_in[6];
    const float* Wev  = (const float*)d_in[7];
    const float* Wss  = (const float*)d_in[8];
    const float* Wvs  = (const float*)d_in[9];
    const float* Wsv  = (const float*)d_in[10];
    const float* Wvv  = (const float*)d_in[11];
    const float* Ls   = (const float*)d_in[12];
    const float* Lv   = (const float*)d_in[13];
    const float* Rw   = (const float*)d_in[14];
    const float* Rb   = (const float*)d_in[15];
    const float* lng  = (const float*)d_in[16];
    const float* lnb  = (const float*)d_in[17];
    const float* Gw   = (const float*)d_in[18];
    const float* Gb   = (const float*)d_in[19];
    const float* Os   = (const float*)d_in[20];
    const float* Ov   = (const float*)d_in[21];
    const float* Psw  = (const float*)d_in[22];
    const float* Psb  = (const float*)d_in[23];
    const float* Pvw  = (const float*)d_in[24];
    const float* Pvb  = (const float*)d_in[25];
    float* out = (float*)d_out;

    static int smem_set = 0;
    if (!smem_set) {
        cudaFuncSetAttribute(k_edge, cudaFuncAttributeMaxDynamicSharedMemorySize, SMEM_BYTES);
        smem_set = 1;
    }

    k_embed<<<(N_NODES / 8 + 3) / 4, 128>>>(x, deg, pos, Wes, Wev, lng, lnb, Gw, Gb);
    for (int l = 0; l < 2; l++) {
        k_edge<<<148, 512, SMEM_BYTES>>>(eidx, evec, elen,
                                         Wss + l * 1024, Wvs + l * 1024,
                                         Wsv + l * 1024, Wvv + l * 1024,
                                         Rw + l * ESC * 128, Rb + l * 128);
        k_node<<<N_NODES / 16, 128>>>(Ls + l * 1024, Lv + l * 1024, l + 1, lng, lnb, Gw, Gb);
    }
    k_out<<<N_NODES / 16, 128>>>(Os, Ov, lng, lnb, Gw, Gb, Psw, Psb, Pvw, Pvb, out);
}

// round 17
// speedup vs baseline: 1.4528x; 1.0235x over previous
#include <cuda_runtime.h>
#include <cstdint>
#include <math.h>

#define N_NODES 50000
#define N_EDGES 800000
#define ESC 50
#define SQRT3F 1.7320508075688772f
#define TP_NORM 0.125f
#define INV_SQRT32 0.17677669529663687f
#define INV_SQRT119 0.09166984970282113f
#define NT 6250

// smem offsets (floats)
#define O_MS 0
#define O_MX 4608
#define O_MY 9216
#define O_MZ 13824
#define O_EL 18432
#define O_BC 26112
#define O_VS 28544
#define O_VV 30208
#define O_RW 31872
#define O_SR 39712
#define O_SB 40224
#define O_EV 56608
#define SMEM_FLOATS 57120
#define SMEM_BYTES (SMEM_FLOATS * 4)
// paired-B strides (floats); all ≡ 8 or 24 mod 32 -> conflict-free LDS.64
#define RW_STR 280
#define BC_STR 152
#define VS_STR 104

__device__ float4 g_state[N_NODES * 32];  // {s, vx, vy, vz} per (node, channel)
__device__ float4 g_agg[N_NODES * 32];    // {s, vx, vy, vz}

__device__ __forceinline__ float sigmoidf_(float x) { return 1.0f / (1.0f + __expf(-x)); }
__device__ __forceinline__ float warp_sum(float v) {
    #pragma unroll
    for (int o = 16; o > 0; o >>= 1) v += __shfl_xor_sync(0xFFFFFFFFu, v, o);
    return v;
}
__device__ __forceinline__ float tf32f(float f) {
    uint32_t r; asm("cvt.rna.tf32.f32 %0, %1;" : "=r"(r) : "f"(f));
    return __uint_as_float(r);
}
__device__ __forceinline__ void cpa4(float* smem_dst, const float* gsrc) {
    uint32_t a = (uint32_t)__cvta_generic_to_shared(smem_dst);
    asm volatile("cp.async.ca.shared.global [%0], [%1], 4;" :: "r"(a), "l"(gsrc));
}
__device__ __forceinline__ void cpa16(float* smem_dst, const float4* gsrc) {
    uint32_t a = (uint32_t)__cvta_generic_to_shared(smem_dst);
    asm volatile("cp.async.cg.shared.global [%0], [%1], 16;" :: "r"(a), "l"(gsrc));
}
#define CP_COMMIT() asm volatile("cp.async.commit_group;" ::: "memory")
#define CP_WAIT0()  asm volatile("cp.async.wait_group 0;" ::: "memory")

#define MMA8(D, a0, a1, a2, a3, b0, b1) \
    asm volatile("mma.sync.aligned.m16n8k8.row.col.f32.tf32.tf32.f32 " \
        "{%0,%1,%2,%3}, {%4,%5,%6,%7}, {%8,%9}, {%0,%1,%2,%3};" \
        : "+f"((D)[0]), "+f"((D)[1]), "+f"((D)[2]), "+f"((D)[3]) \
        : "r"(a0), "r"(a1), "r"(a2), "r"(a3), "r"(b0), "r"(b1))

#define BARP(id) asm volatile("bar.sync %0, %1;" :: "r"(id), "r"(64) : "memory")

// ---------------- node embedding: 8 nodes per warp, weights amortized ----------------
__global__ void k_embed(const float* __restrict__ x, const float* __restrict__ deg,
                        const float* __restrict__ pos,
                        const float* __restrict__ Wes, const float* __restrict__ Wev,
                        const float* __restrict__ lng, const float* __restrict__ lnb,
                        const float* __restrict__ Gw, const float* __restrict__ Gb)
{
    __shared__ float stage[4][8][32];
    int w = threadIdx.x >> 5, lane = threadIdx.x & 31;
    int nb = (blockIdx.x * 4 + w) * 8;
    if (nb >= N_NODES) return;

    float acc[8];
    #pragma unroll
    for (int n = 0; n < 8; n++) acc[n] = 0.f;
    for (int i = 0; i < 59; i++) {
        float w0 = __ldg(Wes + (2 * i) * 32 + lane);
        float w1 = __ldg(Wes + (2 * i + 1) * 32 + lane);
        #pragma unroll
        for (int n = 0; n < 8; n++) {
            float2 v = __ldg((const float2*)(x + (size_t)(nb + n) * 118) + i);
            acc[n] += v.x * w0 + v.y * w1;
        }
    }
    float wd = __ldg(Wes + 118 * 32 + lane);
    float lg = __ldg(lng + lane), lb = __ldg(lnb + lane);
    #pragma unroll
    for (int n = 0; n < 8; n++) {
        float s = (acc[n] + __ldg(deg + nb + n) * wd) * INV_SQRT119;
        float m = warp_sum(s) * (1.0f / 32.0f);
        float d = s - m;
        float var = warp_sum(d * d) * (1.0f / 32.0f);
        float sn = d * rsqrtf(var + 1e-5f) * lg + lb;
        float a = sn * sigmoidf_(sn);
        stage[w][n][lane] = a;
        acc[n] = a;
    }
    __syncwarp();
    float gacc[8];
    float gb = __ldg(Gb + lane);
    #pragma unroll
    for (int n = 0; n < 8; n++) gacc[n] = gb;
    #pragma unroll 8
    for (int i = 0; i < 32; i++) {
        float gw_i = __ldg(Gw + i * 32 + lane);
        #pragma unroll
        for (int n = 0; n < 8; n++) gacc[n] += stage[w][n][i] * gw_i;
    }
    float wv = __ldg(Wev + lane);
    #pragma unroll
    for (int n = 0; n < 8; n++) {
        int nn = nb + n;
        float mg = wv * sigmoidf_(gacc[n]);
        float px = __ldg(pos + nn * 3 + 0), py = __ldg(pos + nn * 3 + 1), pz = __ldg(pos + nn * 3 + 2);
        g_state[nn * 32 + lane] = make_float4(acc[n], px * mg, py * mg, pz * mg);
        g_agg[nn * 32 + lane] = make_float4(0.f, 0.f, 0.f, 0.f);
    }
}

// ---------------- fused edge kernel: paired-B layouts (LDS.64 B-fragments) ----------------
__global__ void __launch_bounds__(512, 1) k_edge(
    const int* __restrict__ eidx, const float* __restrict__ evec,
    const float* __restrict__ elen,
    const float* __restrict__ Wss, const float* __restrict__ Wvs,
    const float* __restrict__ Wsv, const float* __restrict__ Wvv,
    const float* __restrict__ Rw, const float* __restrict__ Rb)
{
    extern __shared__ float sm[];
    float* MS = sm + O_MS;
    float* MX = sm + O_MX;
    float* MY = sm + O_MY;
    float* MZ = sm + O_MZ;
    float* EL = sm + O_EL;
    float* BC = sm + O_BC;   // [16 pairs][72 n][2]
    float* VS = sm + O_VS;   // [16 pairs][40 n][2] (padded stride)
    float* VV = sm + O_VV;
    float* RW = sm + O_RW;   // [28 pairs][136 n][2] (padded stride)
    float4* SR4 = (float4*)(sm + O_SR);
    float* SB = sm + O_SB;
    float* EV = sm + O_EV;

    int tid = threadIdx.x, w = tid >> 5, lane = tid & 31;
    int pair = w >> 1, p = w & 1;
    int g = lane >> 2, c = lane & 3;
    int r0 = pair << 4;
    int rb8 = r0 + (p << 3);
    int barid = 8 + pair;

    // ---- one-time paired B-tile init: pairIdx pp -> rows kk = 8*(pp>>2)+(pp&3) and kk+4 ----
    for (int i = tid; i < 28 * RW_STR; i += 512) {
        int pp = i / RW_STR, r = i % RW_STR;
        float v = 0.f;
        if (r < 272) {
            int n = r >> 1, h = r & 1;
            int kk = ((pp >> 2) << 3) + (pp & 3) + 4 * h;
            if (kk < ESC && n < 128) {
                int ch = n & 31, m = n >> 5;
                int col = (m == 0) ? ch : 32 + 3 * ch + (m - 1);
                v = __ldg(Rw + kk * 128 + col);
            }
        }
        RW[i] = tf32f(v);
    }
    for (int i = tid; i < 16 * BC_STR; i += 512) {
        int pp = i / BC_STR, r = i % BC_STR;
        float v = 0.f;
        if (r < 144) {
            int n = r >> 1, h = r & 1;
            int kk = ((pp >> 2) << 3) + (pp & 3) + 4 * h;
            v = (n < 32) ? __ldg(Wss + kk * 32 + n) : ((n < 64) ? __ldg(Wsv + kk * 32 + n - 32) : 0.f);
        }
        BC[i] = tf32f(v);
    }
    for (int i = tid; i < 16 * VS_STR; i += 512) {
        int pp = i / VS_STR, r = i % VS_STR;
        float v0 = 0.f, v1 = 0.f;
        if (r < 80) {
            int n = r >> 1, h = r & 1;
            int kk = ((pp >> 2) << 3) + (pp & 3) + 4 * h;
            if (n < 32) { v0 = __ldg(Wvs + kk * 32 + n); v1 = __ldg(Wvv + kk * 32 + n); }
        }
        VS[i] = tf32f(v0);
        VV[i] = tf32f(v1);
    }
    for (int i = tid; i < 128 * 10; i += 512)
        EL[(i / 10) * 60 + 50 + (i % 10)] = 0.f;
    __syncthreads();

    float rbv[4][2][2];
    #pragma unroll
    for (int m = 0; m < 4; m++)
        #pragma unroll
        for (int qq = 0; qq < 2; qq++)
            #pragma unroll
            for (int u = 0; u < 2; u++) {
                int ch = 16 * p + 8 * qq + 2 * c + u;
                int col = (m == 0) ? ch : 32 + 3 * ch + (m - 1);
                rbv[m][qq][u] = __ldg(Rb + col);
            }

    int dV = 0, sVn = 0, dVn = 0;

    int t0 = blockIdx.x;
    {
        int sV0 = 0;
        if (lane < 8 && t0 < NT) {
            sV0 = __ldg(eidx + t0 * 128 + rb8 + lane);
            dV  = __ldg(eidx + N_EDGES + t0 * 128 + rb8 + lane);
        }
        if (t0 < NT) {
            int e0n = t0 * 128;
            #pragma unroll
            for (int j = 0; j < 8; j++) {
                int src = __shfl_sync(0xFFFFFFFFu, sV0, j);
                int row = rb8 + j;
                size_t e = (size_t)(e0n + row);
                cpa16(SB + (row * 32 + lane) * 4, &g_state[src * 32 + lane]);
                cpa4(EL + row * 60 + lane, elen + e * ESC + lane);
                if (lane < ESC - 32)
                    cpa4(EL + row * 60 + 32 + lane, elen + e * ESC + 32 + lane);
            }
            if (lane < 24)
                cpa4(EV + (rb8 + lane / 3) * 4 + (lane % 3),
                     evec + (size_t)(e0n + rb8) * 3 + lane);
            CP_COMMIT();
        }
        if (lane < 8 && t0 + (int)gridDim.x < NT) {
            sVn = __ldg(eidx + (t0 + gridDim.x) * 128 + rb8 + lane);
            dVn = __ldg(eidx + N_EDGES + (t0 + gridDim.x) * 128 + rb8 + lane);
        }
    }

    for (int t = t0; t < NT; t += gridDim.x) {
        CP_WAIT0();
        BARP(barid);
        #pragma unroll
        for (int j = 0; j < 8; j++) {
            int row = rb8 + j;
            float4 st = *(const float4*)(SB + (row * 32 + lane) * 4);
            MS[row * 36 + lane] = tf32f(st.x);
            MX[row * 36 + lane] = tf32f(st.y);
            MY[row * 36 + lane] = tf32f(st.z);
            MZ[row * 36 + lane] = tf32f(st.w);
        }
        if (lane < 8) {
            int row = rb8 + lane;
            float vx = EV[row * 4], vy = EV[row * 4 + 1], vz = EV[row * 4 + 2];
            float inv = rsqrtf(vx * vx + vy * vy + vz * vz);
            SR4[row] = make_float4(vx * inv, vy * inv, vz * inv, __int_as_float(dV));
        }
        if (t + (int)gridDim.x < NT) {
            int e0n = (t + gridDim.x) * 128;
            #pragma unroll
            for (int j = 0; j < 8; j++) {
                int src = __shfl_sync(0xFFFFFFFFu, sVn, j);
                int row = rb8 + j;
                cpa16(SB + (row * 32 + lane) * 4, &g_state[src * 32 + lane]);
            }
            if (lane < 24)
                cpa4(EV + (rb8 + lane / 3) * 4 + (lane % 3),
                     evec + (size_t)(e0n + rb8) * 3 + lane);
            CP_COMMIT();
        }
        BARP(barid);

        // ---- phase 1: radial GEMM (paired B: one LDS.64 per mma) ----
        float Cr[8][4];
        #pragma unroll
        for (int i = 0; i < 8; i++) { Cr[i][0] = Cr[i][1] = Cr[i][2] = Cr[i][3] = 0.f; }
        #pragma unroll
        for (int k = 0; k < 7; k++) {
            int k0 = k << 3;
            const float* ab = EL + (r0 + g) * 60 + k0 + c;
            uint32_t a0 = __float_as_uint(ab[0]);
            uint32_t a1 = __float_as_uint(ab[8 * 60]);
            uint32_t a2 = __float_as_uint(ab[4]);
            uint32_t a3 = __float_as_uint(ab[8 * 60 + 4]);
            const float* rwp = RW + (k * 4 + c) * RW_STR + g * 2;
            #pragma unroll
            for (int q = 0; q < 8; q++) {
                int ntg = ((q >> 1) << 2) + (p << 1) + (q & 1);
                float2 b = *(const float2*)(rwp + (ntg << 4));
                MMA8(Cr[q], a0, a1, a2, a3, __float_as_uint(b.x), __float_as_uint(b.y));
            }
        }
        BARP(barid);

        if (t + (int)gridDim.x < NT) {
            int e0n = (t + gridDim.x) * 128;
            #pragma unroll
            for (int j = 0; j < 8; j++) {
                int row = rb8 + j;
                size_t e = (size_t)(e0n + row);
                cpa4(EL + row * 60 + lane, elen + e * ESC + lane);
                if (lane < ESC - 32)
                    cpa4(EL + row * 60 + 32 + lane, elen + e * ESC + 32 + lane);
            }
            CP_COMMIT();
        }
        dV = dVn;
        sVn = 0; dVn = 0;
        if (lane < 8 && t + 2 * (int)gridDim.x < NT) {
            sVn = __ldg(eidx + (t + 2 * gridDim.x) * 128 + rb8 + lane);
            dVn = __ldg(eidx + N_EDGES + (t + 2 * gridDim.x) * 128 + rb8 + lane);
        }

        // ---- phase 2: TP GEMMs + epilogue ----
        float4 rrl = SR4[r0 + g];
        float4 rrh = SR4[r0 + g + 8];
        #pragma unroll
        for (int q = 0; q < 2; q++) {
            int nt = (p << 1) + q;
            int ng2 = ((nt << 3) + g) << 1;
            float cs1[4] = {0,0,0,0}, cs2[4] = {0,0,0,0};
            float cpx[4] = {0,0,0,0}, cpy[4] = {0,0,0,0}, cpz[4] = {0,0,0,0};
            float cax[4] = {0,0,0,0}, cay[4] = {0,0,0,0}, caz[4] = {0,0,0,0};
            #pragma unroll
            for (int k = 0; k < 4; k++) {
                int k0 = k << 3;
                const float* pp;
                pp = MS + (r0 + g) * 36 + k0 + c;
                uint32_t s0 = __float_as_uint(pp[0]), s1 = __float_as_uint(pp[8 * 36]);
                uint32_t s2 = __float_as_uint(pp[4]), s3 = __float_as_uint(pp[8 * 36 + 4]);
                pp = MX + (r0 + g) * 36 + k0 + c;
                uint32_t x0 = __float_as_uint(pp[0]), x1 = __float_as_uint(pp[8 * 36]);
                uint32_t x2 = __float_as_uint(pp[4]), x3 = __float_as_uint(pp[8 * 36 + 4]);
                pp = MY + (r0 + g) * 36 + k0 + c;
                uint32_t y0 = __float_as_uint(pp[0]), y1 = __float_as_uint(pp[8 * 36]);
                uint32_t y2 = __float_as_uint(pp[4]), y3 = __float_as_uint(pp[8 * 36 + 4]);
                pp = MZ + (r0 + g) * 36 + k0 + c;
                uint32_t z0 = __float_as_uint(pp[0]), z1 = __float_as_uint(pp[8 * 36]);
                uint32_t z2 = __float_as_uint(pp[4]), z3 = __float_as_uint(pp[8 * 36 + 4]);

                int pi = k * 4 + c;
                float2 b1v = *(const float2*)(BC + pi * BC_STR + ng2);
                float2 b2v = *(const float2*)(BC + pi * BC_STR + ng2 + 64);
                float2 vsv = *(const float2*)(VS + pi * VS_STR + ng2);
                float2 vvv = *(const float2*)(VV + pi * VS_STR + ng2);

                MMA8(cs1, s0, s1, s2, s3, __float_as_uint(b1v.x), __float_as_uint(b1v.y));
                MMA8(cs2, s0, s1, s2, s3, __float_as_uint(b2v.x), __float_as_uint(b2v.y));
                MMA8(cpx, x0, x1, x2, x3, __float_as_uint(vsv.x), __float_as_uint(vsv.y));
                MMA8(cpy, y0, y1, y2, y3, __float_as_uint(vsv.x), __float_as_uint(vsv.y));
                MMA8(cpz, z0, z1, z2, z3, __float_as_uint(vsv.x), __float_as_uint(vsv.y));
                MMA8(cax, x0, x1, x2, x3, __float_as_uint(vvv.x), __float_as_uint(vvv.y));
                MMA8(cay, y0, y1, y2, y3, __float_as_uint(vvv.x), __float_as_uint(vvv.y));
                MMA8(caz, z0, z1, z2, z3, __float_as_uint(vvv.x), __float_as_uint(vvv.y));
            }
            #pragma unroll
            for (int h = 0; h < 2; h++) {
                float4 rr = h ? rrh : rrl;
                int dst = __float_as_int(rr.w);
                float Yx = SQRT3F * rr.x, Yy = SQRT3F * rr.y, Yz = SQRT3F * rr.z;
                #pragma unroll
                for (int u = 0; u < 2; u++) {
                    int idx = (h << 1) + u;
                    int ch = (nt << 3) + 2 * c + u;
                    float gs = sigmoidf_(Cr[q][idx]     + rbv[0][q][u]);
                    float gx = sigmoidf_(Cr[2 + q][idx] + rbv[1][q][u]);
                    float gy = sigmoidf_(Cr[4 + q][idx] + rbv[2][q][u]);
                    float gz = sigmoidf_(Cr[6 + q][idx] + rbv[3][q][u]);
                    float sOut = (cs1[idx] + rr.x * cpx[idx] + rr.y * cpy[idx]
                                + rr.z * cpz[idx]) * TP_NORM * gs;
                    float sv = cs2[idx];
                    float ovx = (sv * Yx + cax[idx]) * TP_NORM * gx;
                    float ovy = (sv * Yy + cay[idx]) * TP_NORM * gy;
                    float ovz = (sv * Yz + caz[idx]) * TP_NORM * gz;
                    float4* ap = &g_agg[dst * 32 + ch];
                    asm volatile("red.global.add.v4.f32 [%0], {%1,%2,%3,%4};"
                        :: "l"(ap), "f"(sOut), "f"(ovx), "f"(ovy), "f"(ovz) : "memory");
                }
            }
        }
    }
}

// ---------------- node update: 4 nodes per warp ----------------
__global__ void k_node(const float* __restrict__ Ls, const float* __restrict__ Lv,
                       int stage,
                       const float* __restrict__ lng, const float* __restrict__ lnb,
                       const float* __restrict__ Gw, const float* __restrict__ Gb)
{
    __shared__ float sS[4][4][32], sVx[4][4][32], sVy[4][4][32], sVz[4][4][32];
    int w = threadIdx.x >> 5, lane = threadIdx.x & 31;
    int nb = (blockIdx.x * 4 + w) * 4;

    #pragma unroll
    for (int n = 0; n < 4; n++) {
        int nn = nb + n;
        float4 ag = g_agg[nn * 32 + lane];
        g_agg[nn * 32 + lane] = make_float4(0.f, 0.f, 0.f, 0.f);
        float4 st = g_state[nn * 32 + lane];
        sS[w][n][lane] = st.x + ag.x;
        sVx[w][n][lane] = st.y + ag.y;
        sVy[w][n][lane] = st.z + ag.z;
        sVz[w][n][lane] = st.w + ag.w;
    }
    __syncwarp();

    float ns[4] = {0,0,0,0}, nx[4] = {0,0,0,0}, ny[4] = {0,0,0,0}, nz[4] = {0,0,0,0};
    #pragma unroll 8
    for (int i = 0; i < 32; i++) {
        float ls = __ldg(Ls + i * 32 + lane);
        float lv = __ldg(Lv + i * 32 + lane);
        #pragma unroll
        for (int n = 0; n < 4; n++) {
            ns[n] += sS[w][n][i] * ls;
            nx[n] += sVx[w][n][i] * lv;
            ny[n] += sVy[w][n][i] * lv;
            nz[n] += sVz[w][n][i] * lv;
        }
    }
    __syncwarp();

    float lg = __ldg(lng + stage * 32 + lane), lb = __ldg(lnb + stage * 32 + lane);
    #pragma unroll
    for (int n = 0; n < 4; n++) {
        float s = ns[n] * INV_SQRT32;
        float m = warp_sum(s) * (1.0f / 32.0f);
        float d = s - m;
        float var = warp_sum(d * d) * (1.0f / 32.0f);
        float sn = d * rsqrtf(var + 1e-5f) * lg + lb;
        float a = sn * sigmoidf_(sn);
        sS[w][n][lane] = a;
        ns[n] = a;
    }
    __syncwarp();
    float gacc[4];
    float gb = __ldg(Gb + stage * 32 + lane);
    #pragma unroll
    for (int n = 0; n < 4; n++) gacc[n] = gb;
    const float* gw = Gw + stage * 1024;
    #pragma unroll 8
    for (int i = 0; i < 32; i++) {
        float gw_i = __ldg(gw + i * 32 + lane);
        #pragma unroll
        for (int n = 0; n < 4; n++) gacc[n] += sS[w][n][i] * gw_i;
    }
    #pragma unroll
    for (int n = 0; n < 4; n++) {
        float g = sigmoidf_(gacc[n]) * INV_SQRT32;
        g_state[(nb + n) * 32 + lane] = make_float4(ns[n], nx[n] * g, ny[n] * g, nz[n] * g);
    }
}

// ---------------- output head: 4 nodes per warp ----------------
__global__ void k_out(const float* __restrict__ Os, const float* __restrict__ Ov,
                      const float* __restrict__ lng, const float* __restrict__ lnb,
                      const float* __restrict__ Gw, const float* __restrict__ Gb,
                      const float* __restrict__ Psw, const float* __restrict__ Psb,
                      const float* __restrict__ Pvw, const float* __restrict__ Pvb,
                      float* __restrict__ out)
{
    __shared__ float sS[4][4][32], sVx[4][4][32], sVy[4][4][32], sVz[4][4][32];
    int w = threadIdx.x >> 5, lane = threadIdx.x & 31;
    int nb = (blockIdx.x * 4 + w) * 4;

    #pragma unroll
    for (int n = 0; n < 4; n++) {
        float4 st = g_state[(nb + n) * 32 + lane];
        sS[w][n][lane] = st.x;
        sVx[w][n][lane] = st.y;
        sVy[w][n][lane] = st.z;
        sVz[w][n][lane] = st.w;
    }
    __syncwarp();

    float ns[4] = {0,0,0,0}, nx[4] = {0,0,0,0}, ny[4] = {0,0,0,0}, nz[4] = {0,0,0,0};
    #pragma unroll 8
    for (int i = 0; i < 32; i++) {
        float os = __ldg(Os + i * 32 + lane);
        float ov = __ldg(Ov + i * 32 + lane);
        #pragma unroll
        for (int n = 0; n < 4; n++) {
            ns[n] += sS[w][n][i] * os;
            nx[n] += sVx[w][n][i] * ov;
            ny[n] += sVy[w][n][i] * ov;
            nz[n] += sVz[w][n][i] * ov;
        }
    }
    __syncwarp();

    float lg = __ldg(lng + 96 + lane), lb = __ldg(lnb + 96 + lane);
    #pragma unroll
    for (int n = 0; n < 4; n++) {
        float s = ns[n] * INV_SQRT32;
        float m = warp_sum(s) * (1.0f / 32.0f);
        float d = s - m;
        float var = warp_sum(d * d) * (1.0f / 32.0f);
        float sn = d * rsqrtf(var + 1e-5f) * lg + lb;
        float a = sn * sigmoidf_(sn);
        sS[w][n][lane] = a;
    }
    __syncwarp();
    float gacc[4];
    float gb = __ldg(Gb + 96 + lane);
    #pragma unroll
    for (int n = 0; n < 4; n++) gacc[n] = gb;
    const float* gw = Gw + 3 * 1024;
    #pragma unroll 8
    for (int i = 0; i < 32; i++) {
        float gw_i = __ldg(gw + i * 32 + lane);
        #pragma unroll
        for (int n = 0; n < 4; n++) gacc[n] += sS[w][n][i] * gw_i;
    }
    #pragma unroll
    for (int n = 0; n < 4; n++) {
        float g = sigmoidf_(gacc[n]) * INV_SQRT32;
        sVx[w][n][lane] = nx[n] * g;
        sVy[w][n][lane] = ny[n] * g;
        sVz[w][n][lane] = nz[n] * g;
    }
    __syncwarp();

    float sc0[4] = {0,0,0,0}, sc1[4] = {0,0,0,0};
    float t00[4] = {0,0,0,0}, t01[4] = {0,0,0,0};
    float t10[4] = {0,0,0,0}, t11[4] = {0,0,0,0};
    float t20[4] = {0,0,0,0}, t21[4] = {0,0,0,0};
    #pragma unroll 4
    for (int i = 0; i < 32; i++) {
        float pw0 = __ldg(Psw + i * 64 + lane), pw1 = __ldg(Psw + i * 64 + 32 + lane);
        float qw0 = __ldg(Pvw + i * 64 + lane), qw1 = __ldg(Pvw + i * 64 + 32 + lane);
        #pragma unroll
        for (int n = 0; n < 4; n++) {
            float si = sS[w][n][i];
            float vx = sVx[w][n][i], vy = sVy[w][n][i], vz = sVz[w][n][i];
            sc0[n] += si * pw0; sc1[n] += si * pw1;
            t00[n] += vx * qw0; t01[n] += vx * qw1;
            t10[n] += vy * qw0; t11[n] += vy * qw1;
            t20[n] += vz * qw0; t21[n] += vz * qw1;
        }
    }
    float pb0 = __ldg(Psb + lane) + __ldg(Pvb + lane);
    float pb1 = __ldg(Psb + 32 + lane) + __ldg(Pvb + 32 + lane);
    #pragma unroll
    for (int n = 0; n < 4; n++) {
        float base0 = sc0[n] + pb0;
        float base1 = sc1[n] + pb1;
        size_t ob = (size_t)(nb + n) * 192;
        out[ob + lane]       = t00[n] + base0;
        out[ob + 32 + lane]  = t01[n] + base1;
        out[ob + 64 + lane]  = t10[n] + base0;
        out[ob + 96 + lane]  = t11[n] + base1;
        out[ob + 128 + lane] = t20[n] + base0;
        out[ob + 160 + lane] = t21[n] + base1;
    }
}

extern "C" void kernel_launch(void* const* d_in, const int* in_sizes, int n_in,
                              void* d_out, int out_size)
{
    const float* x    = (const float*)d_in[0];
    const float* deg  = (const float*)d_in[1];
    const float* pos  = (const float*)d_in[2];
    const float* evec = (const float*)d_in[3];
    const float* elen = (const float*)d_in[4];
    const int*   eidx = (const int*)d_in[5];
    const float* Wes  = (const float*)d_in[6];
    const float* Wev  = (const float*)d_in[7];
    const float* Wss  = (const float*)d_in[8];
    const float* Wvs  = (const float*)d_in[9];
    const float* Wsv  = (const float*)d_in[10];
    const float* Wvv  = (const float*)d_in[11];
    const float* Ls   = (const float*)d_in[12];
    const float* Lv   = (const float*)d_in[13];
    const float* Rw   = (const float*)d_in[14];
    const float* Rb   = (const float*)d_in[15];
    const float* lng  = (const float*)d_in[16];
    const float* lnb  = (const float*)d_in[17];
    const float* Gw   = (const float*)d_in[18];
    const float* Gb   = (const float*)d_in[19];
    const float* Os   = (const float*)d_in[20];
    const float* Ov   = (const float*)d_in[21];
    const float* Psw  = (const float*)d_in[22];
    const float* Psb  = (const float*)d_in[23];
    const float* Pvw  = (const float*)d_in[24];
    const float* Pvb  = (const float*)d_in[25];
    float* out = (float*)d_out;

    static int smem_set = 0;
    if (!smem_set) {
        cudaFuncSetAttribute(k_edge, cudaFuncAttributeMaxDynamicSharedMemorySize, SMEM_BYTES);
        smem_set = 1;
    }

    k_embed<<<(N_NODES / 8 + 3) / 4, 128>>>(x, deg, pos, Wes, Wev, lng, lnb, Gw, Gb);
    for (int l = 0; l < 2; l++) {
        k_edge<<<148, 512, SMEM_BYTES>>>(eidx, evec, elen,
                                         Wss + l * 1024, Wvs + l * 1024,
                                         Wsv + l * 1024, Wvv + l * 1024,
                                         Rw + l * ESC * 128, Rb + l * 128);
        k_node<<<N_NODES / 16, 128>>>(Ls + l * 1024, Lv + l * 1024, l + 1, lng, lnb, Gw, Gb);
    }
    k_out<<<N_NODES / 16, 128>>>(Os, Ov, lng, lnb, Gw, Gb, Psw, Psb, Pvw, Pvb, out);
}